// round 13
// baseline (speedup 1.0000x reference)
#include <cuda_runtime.h>

#define NN     50000
#define NP     50048
#define EE     800000
#define NHD    4
#define NC     32
#define HC     128
#define NL     3
#define OUTC   10
#define CAP    96
#define BN_EPS 1e-5f

// ---------------- static device scratch ----------------
__device__ __align__(16) float g_buf0[HC * NP];     // channel-major
__device__ __align__(16) float g_buf1[HC * NP];
__device__ __align__(16) float g_y[NN * NC];        // row-major
__device__ __align__(16) float g_as[NN * NHD];
__device__ __align__(16) float g_ad[NN * NHD];
__device__ float g_sumL[NL][HC];
__device__ float g_sqL[NL][HC];
__device__ __align__(16) float g_linT[HC * NC];     // folded lin_W [k][c]
__device__ float g_const[NC];
__device__ float g_attF[NL][2][HC];                 // static per-layer folds
__device__ __align__(16) float g_rF[OUTC * HC];
__device__ float g_rc[OUTC];
__device__ int   g_deg[NN];
__device__ int   g_pad[NN * CAP];

__device__ __forceinline__ float* bufPtr(int b) { return b ? g_buf1 : g_buf0; }

__device__ __forceinline__ float lrelu_exp(float z) {
    z = (z > 0.f) ? z : 0.2f * z;
    return __expf(z);
}

// ---------------- kernels ----------------

// init + ALL static (BN-independent) weight folds, block-range split.
__global__ void __launch_bounds__(256)
k_init(float* __restrict__ out, int out_n, int N, int nInit,
       const float* __restrict__ gatW, const float* __restrict__ attS,
       const float* __restrict__ attD, const float* __restrict__ gatb,
       const float* __restrict__ rW, const float* __restrict__ rb) {
    int b = blockIdx.x;
    int tid = threadIdx.x;
    if (b < nInit) {
        int gid = b * 256 + tid;
        if (gid < N) g_deg[gid] = 0;
        if (gid < NL * HC) { (&g_sumL[0][0])[gid] = 0.f; (&g_sqL[0][0])[gid] = 0.f; }
        if (gid < out_n) out[gid] = 0.f;
    } else if (b < nInit + NL) {
        // attF for layer l = b - nInit   (128 active threads)
        int l = b - nInit;
        if (tid < HC) {
            int hd = tid >> 5, cc = tid & 31;
            float a = 0.f, d = 0.f;
            for (int j = 0; j < 32; j++) {
                int r = hd * 32 + j;
                float w = __ldg(&gatW[l * HC * NC + r * NC + cc]);
                a = fmaf(w, __ldg(&attS[l * HC + r]), a);
                d = fmaf(w, __ldg(&attD[l * HC + r]), d);
            }
            g_attF[l][0][tid] = a;
            g_attF[l][1][tid] = d;
        }
    } else {
        // rF = rW·gatW (last layer), rc = rW·gatb + rb
        int l = NL - 1;
        if (tid < HC) {
            int i = tid >> 5, cp = tid & 31;
#pragma unroll
            for (int o = 0; o < OUTC; o++) {
                float v = 0.f;
                for (int j = 0; j < 32; j++) {
                    int k = i * 32 + j;
                    v = fmaf(__ldg(&rW[o * HC + k]),
                             __ldg(&gatW[l * HC * NC + k * NC + cp]), v);
                }
                g_rF[o * HC + tid] = v;
            }
        }
        if (tid >= 128 && tid < 128 + OUTC) {
            int o = tid - 128;
            float v = rb[o];
            for (int k = 0; k < HC; k++)
                v = fmaf(__ldg(&rW[o * HC + k]), __ldg(&gatb[l * HC + k]), v);
            g_rc[o] = v;
        }
    }
}

// [0,nA): embed gather (channel-major) + layer-0 BN stats.  [nA,...): padded-CSR scatter.
__global__ void __launch_bounds__(256)
k_embed_scatter(const int* __restrict__ xidx, const float* __restrict__ embed,
                const int* __restrict__ ei, int N, int E, int nA) {
    int tid = threadIdx.x;
    if ((int)blockIdx.x < nA) {
        __shared__ float sS[2][HC], sQ[2][HC];
        __shared__ float sT[64][129];
        int c = tid & 127, sub = tid >> 7;
        int r0 = blockIdx.x * 64;
        float s = 0.f, s2 = 0.f;
#pragma unroll 4
        for (int it = 0; it < 32; it++) {
            int rl = sub + it * 2;
            int r = r0 + rl;
            float v = 0.f;
            if (r < N) {
                v = embed[xidx[r] * HC + c];
                s += v; s2 += v * v;
            }
            sT[rl][c] = v;
        }
        sS[sub][c] = s; sQ[sub][c] = s2;
        __syncthreads();
        if (tid < HC) {
            atomicAdd(&g_sumL[0][tid], sS[0][tid] + sS[1][tid]);
            atomicAdd(&g_sqL[0][tid], sQ[0][tid] + sQ[1][tid]);
        }
        int node = tid & 63;
        int cb = tid >> 6;
        int r = r0 + node;
        if (r < N) {
#pragma unroll
            for (int p = 0; p < 32; p++) {
                int cc = cb * 32 + p;
                g_buf0[cc * NP + r] = sT[node][cc];
            }
        }
    } else {
        int gid = (blockIdx.x - nA) * 256 + tid;
        if (gid < E) {
            int s = ei[gid], d = ei[E + gid];
            int pos = atomicAdd(&g_deg[d], 1);
            g_pad[d * CAP + pos] = s;
        }
    }
}

// Per-layer BN-dependent folding only (one block): linT + const.
__global__ void __launch_bounds__(128)
k_prep(int l,
       const float* __restrict__ linW, const float* __restrict__ linb,
       const float* __restrict__ bng, const float* __restrict__ bnb, int N) {
    __shared__ float sShift[HC];
    int tid = threadIdx.x;
    float scale;
    {
        float invN = 1.0f / (float)N;
        float mean = g_sumL[l][tid] * invN;
        float var  = g_sqL[l][tid] * invN - mean * mean;
        float rstd = rsqrtf(var + BN_EPS);
        scale = bng[l * HC + tid] * rstd;
        sShift[tid] = bnb[l * HC + tid] - scale * mean;
    }
    __syncthreads();
    // each thread owns channel k = tid; folds all 32 c for that k (coalesced-ish via L2)
    {
        int k = tid;
#pragma unroll
        for (int c = 0; c < NC; c++)
            g_linT[k * NC + c] = __ldg(&linW[l * NC * HC + c * HC + k]) * scale;
    }
    if (tid < NC) {
        float cst = linb[l * NC + tid];
        const float* lw = &linW[l * NC * HC + tid * HC];
#pragma unroll 4
        for (int k = 0; k < HC; k++) cst = fmaf(__ldg(&lw[k]), sShift[k], cst);
        g_const[tid] = cst;
    }
}

// Per-node GEMM: one thread per node, channel-major x, batched LDGs (MLP=8).
__global__ void __launch_bounds__(128)
k_node(int inB, int l, int N) {
    __shared__ __align__(16) float sLinT[HC * NC];
    __shared__ __align__(16) float sY[128 * 33];
    __shared__ float sAs[HC], sAd[HC], sConst[NC];

    int tid = threadIdx.x;
    for (int i = tid; i < HC * NC; i += 128) sLinT[i] = g_linT[i];
    if (tid < HC) { sAs[tid] = g_attF[l][0][tid]; sAd[tid] = g_attF[l][1][tid]; }
    if (tid < NC) sConst[tid] = g_const[tid];
    __syncthreads();

    int n0 = blockIdx.x * 128;
    int n = n0 + tid;
    const float* __restrict__ xb = bufPtr(inB);

    float y[NC];
#pragma unroll
    for (int c = 0; c < NC; c++) y[c] = sConst[c];

#pragma unroll 2
    for (int kb = 0; kb < HC; kb += 8) {
        float xv[8];
#pragma unroll
        for (int u = 0; u < 8; u++) xv[u] = xb[(kb + u) * NP + n];
#pragma unroll
        for (int u = 0; u < 8; u++) {
            const float4* wr = reinterpret_cast<const float4*>(&sLinT[(kb + u) * NC]);
            float xu = xv[u];
#pragma unroll
            for (int q = 0; q < 8; q++) {
                float4 w = wr[q];
                y[4 * q]     = fmaf(xu, w.x, y[4 * q]);
                y[4 * q + 1] = fmaf(xu, w.y, y[4 * q + 1]);
                y[4 * q + 2] = fmaf(xu, w.z, y[4 * q + 2]);
                y[4 * q + 3] = fmaf(xu, w.w, y[4 * q + 3]);
            }
        }
    }
#pragma unroll
    for (int c = 0; c < NC; c++) y[c] = fmaxf(y[c], 0.f);

    if (n < N) {
        float as[NHD] = {0.f, 0.f, 0.f, 0.f}, ad[NHD] = {0.f, 0.f, 0.f, 0.f};
#pragma unroll
        for (int hd = 0; hd < NHD; hd++) {
#pragma unroll
            for (int c = 0; c < NC; c++) {
                as[hd] = fmaf(y[c], sAs[hd * 32 + c], as[hd]);
                ad[hd] = fmaf(y[c], sAd[hd * 32 + c], ad[hd]);
            }
        }
        *reinterpret_cast<float4*>(&g_as[n * NHD]) = make_float4(as[0], as[1], as[2], as[3]);
        *reinterpret_cast<float4*>(&g_ad[n * NHD]) = make_float4(ad[0], ad[1], ad[2], ad[3]);
    }

    __syncthreads();
#pragma unroll
    for (int c = 0; c < NC; c++) sY[tid * 33 + c] = y[c];
    __syncthreads();
#pragma unroll
    for (int j = 0; j < 32; j++) {
        int i = tid + j * 128;
        int ni = i >> 5, ci = i & 31;
        int nn = n0 + ni;
        if (nn < N) g_y[nn * NC + ci] = sY[ni * 33 + ci];
    }
}

// Gather: ONE WARP PER NODE (8 nodes/block). Group-parallel edge consume,
// vectorized projection (mode 0), folded readout (mode 1).
__global__ void __launch_bounds__(256)
k_gather(int outB, const float* __restrict__ gatW, const float* __restrict__ gatb,
         const int* __restrict__ batch, float* __restrict__ out,
         int l, int N, int mode) {
    __shared__ __align__(16) float sGatW[HC * 36];   // mode0: pad-36 weights; mode1: rF
    __shared__ __align__(16) float4 sW[8][32];
    __shared__ int sS[8][32];
    __shared__ __align__(16) float sOut[8][132];
    __shared__ float sGatB[HC];

    int tid = threadIdx.x;
    int wid = tid >> 5, lane = tid & 31;
    if (mode == 0) {
        for (int m = tid; m < HC * NC; m += 256) {
            int r = m >> 5, c = m & 31;
            sGatW[r * 36 + c] = gatW[l * HC * NC + m];
        }
        if (tid < HC) sGatB[tid] = gatb[l * HC + tid];
    } else {
        for (int m = tid; m < OUTC * HC; m += 256) sGatW[m] = g_rF[m];
        if (tid < OUTC) sGatB[tid] = g_rc[tid];
    }
    __syncthreads();

    int hd = lane >> 3, q = lane & 7;
    int grp = lane >> 3;
    const float* __restrict__ ybase = g_y;

    int gw = blockIdx.x * 8 + wid;
    bool valid = (gw < N);
    int gws = valid ? gw : 0;

    int cnt = valid ? g_deg[gws] : 0;
    const int* __restrict__ lst = &g_pad[gws * CAP];
    float4 ad4 = make_float4(0.f, 0.f, 0.f, 0.f);
    float4 asSelf = make_float4(0.f, 0.f, 0.f, 0.f);
    if (valid) {
        ad4 = *reinterpret_cast<const float4*>(&g_ad[gws * NHD]);
        asSelf = *reinterpret_cast<const float4*>(&g_as[gws * NHD]);
    }
    float4 wself;
    wself.x = lrelu_exp(asSelf.x + ad4.x);
    wself.y = lrelu_exp(asSelf.y + ad4.y);
    wself.z = lrelu_exp(asSelf.z + ad4.z);
    wself.w = lrelu_exp(asSelf.w + ad4.w);

    float4 accH0 = make_float4(0.f, 0.f, 0.f, 0.f);
    float4 accH1 = make_float4(0.f, 0.f, 0.f, 0.f);
    float4 accH2 = make_float4(0.f, 0.f, 0.f, 0.f);
    float4 accH3 = make_float4(0.f, 0.f, 0.f, 0.f);
    float4 wsum4 = make_float4(0.f, 0.f, 0.f, 0.f);

    for (int base = 0; base < cnt; base += 32) {
        int c2 = min(32, cnt - base);
        int s_l = 0;
        float4 w4 = make_float4(0.f, 0.f, 0.f, 0.f);
        if (lane < c2) {
            s_l = lst[base + lane];
            const float4 as4 = *reinterpret_cast<const float4*>(&g_as[s_l * NHD]);
            w4.x = lrelu_exp(as4.x + ad4.x);
            w4.y = lrelu_exp(as4.y + ad4.y);
            w4.z = lrelu_exp(as4.z + ad4.z);
            w4.w = lrelu_exp(as4.w + ad4.w);
        }
        wsum4.x += w4.x; wsum4.y += w4.y; wsum4.z += w4.z; wsum4.w += w4.w;
        sS[wid][lane] = s_l;
        sW[wid][lane] = w4;
        __syncwarp();

        int j = grp;
        for (; j + 4 < c2; j += 8) {
            int sA = sS[wid][j], sB = sS[wid][j + 4];
            float4 weA = sW[wid][j], weB = sW[wid][j + 4];
            const float4 yA = *reinterpret_cast<const float4*>(&ybase[sA * NC + q * 4]);
            const float4 yB = *reinterpret_cast<const float4*>(&ybase[sB * NC + q * 4]);
            accH0.x = fmaf(weA.x, yA.x, accH0.x); accH0.y = fmaf(weA.x, yA.y, accH0.y);
            accH0.z = fmaf(weA.x, yA.z, accH0.z); accH0.w = fmaf(weA.x, yA.w, accH0.w);
            accH1.x = fmaf(weA.y, yA.x, accH1.x); accH1.y = fmaf(weA.y, yA.y, accH1.y);
            accH1.z = fmaf(weA.y, yA.z, accH1.z); accH1.w = fmaf(weA.y, yA.w, accH1.w);
            accH2.x = fmaf(weA.z, yA.x, accH2.x); accH2.y = fmaf(weA.z, yA.y, accH2.y);
            accH2.z = fmaf(weA.z, yA.z, accH2.z); accH2.w = fmaf(weA.z, yA.w, accH2.w);
            accH3.x = fmaf(weA.w, yA.x, accH3.x); accH3.y = fmaf(weA.w, yA.y, accH3.y);
            accH3.z = fmaf(weA.w, yA.z, accH3.z); accH3.w = fmaf(weA.w, yA.w, accH3.w);
            accH0.x = fmaf(weB.x, yB.x, accH0.x); accH0.y = fmaf(weB.x, yB.y, accH0.y);
            accH0.z = fmaf(weB.x, yB.z, accH0.z); accH0.w = fmaf(weB.x, yB.w, accH0.w);
            accH1.x = fmaf(weB.y, yB.x, accH1.x); accH1.y = fmaf(weB.y, yB.y, accH1.y);
            accH1.z = fmaf(weB.y, yB.z, accH1.z); accH1.w = fmaf(weB.y, yB.w, accH1.w);
            accH2.x = fmaf(weB.z, yB.x, accH2.x); accH2.y = fmaf(weB.z, yB.y, accH2.y);
            accH2.z = fmaf(weB.z, yB.z, accH2.z); accH2.w = fmaf(weB.z, yB.w, accH2.w);
            accH3.x = fmaf(weB.w, yB.x, accH3.x); accH3.y = fmaf(weB.w, yB.y, accH3.y);
            accH3.z = fmaf(weB.w, yB.z, accH3.z); accH3.w = fmaf(weB.w, yB.w, accH3.w);
        }
        if (j < c2) {
            int sA = sS[wid][j];
            float4 weA = sW[wid][j];
            const float4 yA = *reinterpret_cast<const float4*>(&ybase[sA * NC + q * 4]);
            accH0.x = fmaf(weA.x, yA.x, accH0.x); accH0.y = fmaf(weA.x, yA.y, accH0.y);
            accH0.z = fmaf(weA.x, yA.z, accH0.z); accH0.w = fmaf(weA.x, yA.w, accH0.w);
            accH1.x = fmaf(weA.y, yA.x, accH1.x); accH1.y = fmaf(weA.y, yA.y, accH1.y);
            accH1.z = fmaf(weA.y, yA.z, accH1.z); accH1.w = fmaf(weA.y, yA.w, accH1.w);
            accH2.x = fmaf(weA.z, yA.x, accH2.x); accH2.y = fmaf(weA.z, yA.y, accH2.y);
            accH2.z = fmaf(weA.z, yA.z, accH2.z); accH2.w = fmaf(weA.z, yA.w, accH2.w);
            accH3.x = fmaf(weA.w, yA.x, accH3.x); accH3.y = fmaf(weA.w, yA.y, accH3.y);
            accH3.z = fmaf(weA.w, yA.z, accH3.z); accH3.w = fmaf(weA.w, yA.w, accH3.w);
        }
        __syncwarp();
    }

#pragma unroll
    for (int off = 8; off <= 16; off <<= 1) {
        accH0.x += __shfl_xor_sync(0xffffffffu, accH0.x, off);
        accH0.y += __shfl_xor_sync(0xffffffffu, accH0.y, off);
        accH0.z += __shfl_xor_sync(0xffffffffu, accH0.z, off);
        accH0.w += __shfl_xor_sync(0xffffffffu, accH0.w, off);
        accH1.x += __shfl_xor_sync(0xffffffffu, accH1.x, off);
        accH1.y += __shfl_xor_sync(0xffffffffu, accH1.y, off);
        accH1.z += __shfl_xor_sync(0xffffffffu, accH1.z, off);
        accH1.w += __shfl_xor_sync(0xffffffffu, accH1.w, off);
        accH2.x += __shfl_xor_sync(0xffffffffu, accH2.x, off);
        accH2.y += __shfl_xor_sync(0xffffffffu, accH2.y, off);
        accH2.z += __shfl_xor_sync(0xffffffffu, accH2.z, off);
        accH2.w += __shfl_xor_sync(0xffffffffu, accH2.w, off);
        accH3.x += __shfl_xor_sync(0xffffffffu, accH3.x, off);
        accH3.y += __shfl_xor_sync(0xffffffffu, accH3.y, off);
        accH3.z += __shfl_xor_sync(0xffffffffu, accH3.z, off);
        accH3.w += __shfl_xor_sync(0xffffffffu, accH3.w, off);
    }
    float4 acc = (hd == 0) ? accH0 : (hd == 1) ? accH1 : (hd == 2) ? accH2 : accH3;

#pragma unroll
    for (int off = 16; off; off >>= 1) {
        wsum4.x += __shfl_xor_sync(0xffffffffu, wsum4.x, off);
        wsum4.y += __shfl_xor_sync(0xffffffffu, wsum4.y, off);
        wsum4.z += __shfl_xor_sync(0xffffffffu, wsum4.z, off);
        wsum4.w += __shfl_xor_sync(0xffffffffu, wsum4.w, off);
    }
    wsum4.x += wself.x; wsum4.y += wself.y; wsum4.z += wself.z; wsum4.w += wself.w;
    float wsh = (hd == 0) ? wself.x : (hd == 1) ? wself.y : (hd == 2) ? wself.z : wself.w;
    const float4 ys = *reinterpret_cast<const float4*>(&ybase[gws * NC + q * 4]);
    acc.x = fmaf(wsh, ys.x, acc.x); acc.y = fmaf(wsh, ys.y, acc.y);
    acc.z = fmaf(wsh, ys.z, acc.z); acc.w = fmaf(wsh, ys.w, acc.w);
    float wsumh = (hd == 0) ? wsum4.x : (hd == 1) ? wsum4.y : (hd == 2) ? wsum4.z : wsum4.w;
    float inv = 1.f / (wsumh + 1e-16f);
    acc.x *= inv; acc.y *= inv; acc.z *= inv; acc.w *= inv;

    if (mode == 0) {
        // stash normalized agg head-major (lane*4 == hd*32 + q*4)
        *reinterpret_cast<float4*>(&sOut[wid][lane * 4]) = acc;
        __syncwarp();

        float a[4];
#pragma unroll
        for (int i = 0; i < 4; i++) {
            int o = lane + 32 * i;
            float v = sGatB[o];
            const float4* aggh4 = reinterpret_cast<const float4*>(&sOut[wid][i * 32]);
            const float4* w4p = reinterpret_cast<const float4*>(&sGatW[o * 36]);
#pragma unroll
            for (int j = 0; j < 8; j++) {
                float4 ag = aggh4[j];
                float4 w = w4p[j];
                v = fmaf(ag.x, w.x, v);
                v = fmaf(ag.y, w.y, v);
                v = fmaf(ag.z, w.z, v);
                v = fmaf(ag.w, w.w, v);
            }
            a[i] = valid ? v : 0.f;
        }
        __syncwarp();
#pragma unroll
        for (int i = 0; i < 4; i++) sOut[wid][lane + 32 * i] = a[i];

        __syncthreads();
        // next-layer BN stats (8 nodes)
        if (tid < HC) {
            float s = 0.f, s2 = 0.f;
#pragma unroll
            for (int w = 0; w < 8; w++) {
                float v = sOut[w][tid];
                s += v; s2 += v * v;
            }
            atomicAdd(&g_sumL[l + 1][tid], s);
            atomicAdd(&g_sqL[l + 1][tid], s2);
        }
        // channel-major feature write: 8 consecutive nodes per 32B sector
        float* ob = bufPtr(outB);
        int node = tid & 7;
        int gw2 = blockIdx.x * 8 + node;
        if (gw2 < N) {
            int cb = tid >> 3;   // 0..31, 4 channels each
#pragma unroll
            for (int p = 0; p < 4; p++) {
                int cc = cb * 4 + p;
                ob[cc * NP + gw2] = sOut[node][cc];
            }
        }
    } else if (valid) {
        int g = batch[gw];
#pragma unroll
        for (int o = 0; o < OUTC; o++) {
            const float4 rf = *reinterpret_cast<const float4*>(&sGatW[o * HC + lane * 4]);
            float p = acc.x * rf.x + acc.y * rf.y + acc.z * rf.z + acc.w * rf.w;
#pragma unroll
            for (int off = 16; off; off >>= 1)
                p += __shfl_xor_sync(0xffffffffu, p, off);
            if (lane == o) atomicAdd(&out[g * OUTC + o], p + sGatB[o]);
        }
    }
}

// ---------------- launch ----------------
extern "C" void kernel_launch(void* const* d_in, const int* in_sizes, int n_in,
                              void* d_out, int out_size) {
    const int*   xidx  = (const int*)d_in[0];
    const int*   ei    = (const int*)d_in[1];
    const int*   batch = (const int*)d_in[2];
    const float* embed = (const float*)d_in[3];
    const float* bng   = (const float*)d_in[4];
    const float* bnb   = (const float*)d_in[5];
    const float* linW  = (const float*)d_in[6];
    const float* linb  = (const float*)d_in[7];
    const float* gatW  = (const float*)d_in[8];
    const float* attS  = (const float*)d_in[9];
    const float* attD  = (const float*)d_in[10];
    const float* gatb  = (const float*)d_in[11];
    const float* rW    = (const float*)d_in[12];
    const float* rb    = (const float*)d_in[13];
    float* out = (float*)d_out;

    int N = in_sizes[0];
    int E = in_sizes[1] / 2;
    int nInit = (N + 255) / 256;
    int nA = (N + 63) / 64;
    int nB = (E + 255) / 256;

    k_init<<<nInit + NL + 1, 256>>>(out, out_size, N, nInit, gatW, attS, attD, gatb, rW, rb);
    k_embed_scatter<<<nA + nB, 256>>>(xidx, embed, ei, N, E, nA);

    for (int l = 0; l < NL; l++) {
        int inB = l & 1;
        int outB = inB ^ 1;
        int mode = (l == NL - 1) ? 1 : 0;
        k_prep<<<1, 128>>>(l, linW, linb, bng, bnb, N);
        k_node<<<(N + 127) / 128, 128>>>(inB, l, N);
        k_gather<<<(N + 7) / 8, 256>>>(outB, gatW, gatb, batch, out, l, N, mode);
    }
}

// round 14
// speedup vs baseline: 1.3051x; 1.3051x over previous
#include <cuda_runtime.h>

#define NN     50000
#define NP     50048
#define EE     800000
#define NHD    4
#define NC     32
#define HC     128
#define NL     3
#define OUTC   10
#define CAP    96
#define BN_EPS 1e-5f

// ---------------- static device scratch ----------------
__device__ __align__(16) float g_buf0[HC * NP];     // channel-major
__device__ __align__(16) float g_buf1[HC * NP];
__device__ __align__(16) float g_y[NN * NC];        // row-major
__device__ __align__(16) float g_as[NN * NHD];
__device__ __align__(16) float g_ad[NN * NHD];
__device__ float g_sumL[NL][HC];
__device__ float g_sqL[NL][HC];
__device__ __align__(16) float g_linT[HC * NC];     // folded lin_W [k][c]
__device__ float g_const[NC];
__device__ float g_attF[NL][2][HC];                 // static per-layer folds
__device__ __align__(16) float g_rF[OUTC * HC];
__device__ float g_rc[OUTC];
__device__ int   g_deg[NN];
__device__ int   g_pad[NN * CAP];

__device__ __forceinline__ float* bufPtr(int b) { return b ? g_buf1 : g_buf0; }

__device__ __forceinline__ float lrelu_exp(float z) {
    z = (z > 0.f) ? z : 0.2f * z;
    return __expf(z);
}

// ---------------- kernels ----------------

// init + ALL static (BN-independent) weight folds, block-range split.
__global__ void __launch_bounds__(256)
k_init(float* __restrict__ out, int out_n, int N, int nInit,
       const float* __restrict__ gatW, const float* __restrict__ attS,
       const float* __restrict__ attD, const float* __restrict__ gatb,
       const float* __restrict__ rW, const float* __restrict__ rb) {
    int b = blockIdx.x;
    int tid = threadIdx.x;
    if (b < nInit) {
        int gid = b * 256 + tid;
        if (gid < N) g_deg[gid] = 0;
        if (gid < NL * HC) { (&g_sumL[0][0])[gid] = 0.f; (&g_sqL[0][0])[gid] = 0.f; }
        if (gid < out_n) out[gid] = 0.f;
    } else if (b < nInit + NL) {
        int l = b - nInit;
        if (tid < HC) {
            int hd = tid >> 5, cc = tid & 31;
            float a = 0.f, d = 0.f;
            for (int j = 0; j < 32; j++) {
                int r = hd * 32 + j;
                float w = __ldg(&gatW[l * HC * NC + r * NC + cc]);
                a = fmaf(w, __ldg(&attS[l * HC + r]), a);
                d = fmaf(w, __ldg(&attD[l * HC + r]), d);
            }
            g_attF[l][0][tid] = a;
            g_attF[l][1][tid] = d;
        }
    } else {
        int l = NL - 1;
        if (tid < HC) {
            int i = tid >> 5, cp = tid & 31;
#pragma unroll
            for (int o = 0; o < OUTC; o++) {
                float v = 0.f;
                for (int j = 0; j < 32; j++) {
                    int k = i * 32 + j;
                    v = fmaf(__ldg(&rW[o * HC + k]),
                             __ldg(&gatW[l * HC * NC + k * NC + cp]), v);
                }
                g_rF[o * HC + tid] = v;
            }
        }
        if (tid >= 128 && tid < 128 + OUTC) {
            int o = tid - 128;
            float v = rb[o];
            for (int k = 0; k < HC; k++)
                v = fmaf(__ldg(&rW[o * HC + k]), __ldg(&gatb[l * HC + k]), v);
            g_rc[o] = v;
        }
    }
}

// [0,nA): embed gather (channel-major) + layer-0 BN stats.  [nA,...): padded-CSR scatter.
__global__ void __launch_bounds__(256)
k_embed_scatter(const int* __restrict__ xidx, const float* __restrict__ embed,
                const int* __restrict__ ei, int N, int E, int nA) {
    int tid = threadIdx.x;
    if ((int)blockIdx.x < nA) {
        __shared__ float sS[2][HC], sQ[2][HC];
        __shared__ float sT[64][129];
        int c = tid & 127, sub = tid >> 7;
        int r0 = blockIdx.x * 64;
        float s = 0.f, s2 = 0.f;
#pragma unroll 4
        for (int it = 0; it < 32; it++) {
            int rl = sub + it * 2;
            int r = r0 + rl;
            float v = 0.f;
            if (r < N) {
                v = embed[xidx[r] * HC + c];
                s += v; s2 += v * v;
            }
            sT[rl][c] = v;
        }
        sS[sub][c] = s; sQ[sub][c] = s2;
        __syncthreads();
        if (tid < HC) {
            atomicAdd(&g_sumL[0][tid], sS[0][tid] + sS[1][tid]);
            atomicAdd(&g_sqL[0][tid], sQ[0][tid] + sQ[1][tid]);
        }
        int node = tid & 63;
        int cb = tid >> 6;
        int r = r0 + node;
        if (r < N) {
#pragma unroll
            for (int p = 0; p < 32; p++) {
                int cc = cb * 32 + p;
                g_buf0[cc * NP + r] = sT[node][cc];
            }
        }
    } else {
        int gid = (blockIdx.x - nA) * 256 + tid;
        if (gid < E) {
            int s = ei[gid], d = ei[E + gid];
            int pos = atomicAdd(&g_deg[d], 1);
            g_pad[d * CAP + pos] = s;
        }
    }
}

// Per-layer BN-dependent folding only (one block): linT + const.
__global__ void __launch_bounds__(128)
k_prep(int l,
       const float* __restrict__ linW, const float* __restrict__ linb,
       const float* __restrict__ bng, const float* __restrict__ bnb, int N) {
    __shared__ float sShift[HC];
    int tid = threadIdx.x;
    float scale;
    {
        float invN = 1.0f / (float)N;
        float mean = g_sumL[l][tid] * invN;
        float var  = g_sqL[l][tid] * invN - mean * mean;
        float rstd = rsqrtf(var + BN_EPS);
        scale = bng[l * HC + tid] * rstd;
        sShift[tid] = bnb[l * HC + tid] - scale * mean;
    }
    __syncthreads();
    {
        int k = tid;
#pragma unroll
        for (int c = 0; c < NC; c++)
            g_linT[k * NC + c] = __ldg(&linW[l * NC * HC + c * HC + k]) * scale;
    }
    if (tid < NC) {
        float cst = linb[l * NC + tid];
        const float* lw = &linW[l * NC * HC + tid * HC];
#pragma unroll 4
        for (int k = 0; k < HC; k++) cst = fmaf(__ldg(&lw[k]), sShift[k], cst);
        g_const[tid] = cst;
    }
}

// Per-node GEMM: one thread per node, channel-major x, batched LDGs (MLP=8).
__global__ void __launch_bounds__(128)
k_node(int inB, int l, int N) {
    __shared__ __align__(16) float sLinT[HC * NC];
    __shared__ __align__(16) float sY[128 * 33];
    __shared__ float sAs[HC], sAd[HC], sConst[NC];

    int tid = threadIdx.x;
    for (int i = tid; i < HC * NC; i += 128) sLinT[i] = g_linT[i];
    if (tid < HC) { sAs[tid] = g_attF[l][0][tid]; sAd[tid] = g_attF[l][1][tid]; }
    if (tid < NC) sConst[tid] = g_const[tid];
    __syncthreads();

    int n0 = blockIdx.x * 128;
    int n = n0 + tid;
    const float* __restrict__ xb = bufPtr(inB);

    float y[NC];
#pragma unroll
    for (int c = 0; c < NC; c++) y[c] = sConst[c];

#pragma unroll 2
    for (int kb = 0; kb < HC; kb += 8) {
        float xv[8];
#pragma unroll
        for (int u = 0; u < 8; u++) xv[u] = xb[(kb + u) * NP + n];
#pragma unroll
        for (int u = 0; u < 8; u++) {
            const float4* wr = reinterpret_cast<const float4*>(&sLinT[(kb + u) * NC]);
            float xu = xv[u];
#pragma unroll
            for (int q = 0; q < 8; q++) {
                float4 w = wr[q];
                y[4 * q]     = fmaf(xu, w.x, y[4 * q]);
                y[4 * q + 1] = fmaf(xu, w.y, y[4 * q + 1]);
                y[4 * q + 2] = fmaf(xu, w.z, y[4 * q + 2]);
                y[4 * q + 3] = fmaf(xu, w.w, y[4 * q + 3]);
            }
        }
    }
#pragma unroll
    for (int c = 0; c < NC; c++) y[c] = fmaxf(y[c], 0.f);

    if (n < N) {
        float as[NHD] = {0.f, 0.f, 0.f, 0.f}, ad[NHD] = {0.f, 0.f, 0.f, 0.f};
#pragma unroll
        for (int hd = 0; hd < NHD; hd++) {
#pragma unroll
            for (int c = 0; c < NC; c++) {
                as[hd] = fmaf(y[c], sAs[hd * 32 + c], as[hd]);
                ad[hd] = fmaf(y[c], sAd[hd * 32 + c], ad[hd]);
            }
        }
        *reinterpret_cast<float4*>(&g_as[n * NHD]) = make_float4(as[0], as[1], as[2], as[3]);
        *reinterpret_cast<float4*>(&g_ad[n * NHD]) = make_float4(ad[0], ad[1], ad[2], ad[3]);
    }

    __syncthreads();
#pragma unroll
    for (int c = 0; c < NC; c++) sY[tid * 33 + c] = y[c];
    __syncthreads();
#pragma unroll
    for (int j = 0; j < 32; j++) {
        int i = tid + j * 128;
        int ni = i >> 5, ci = i & 31;
        int nn = n0 + ni;
        if (nn < N) g_y[nn * NC + ci] = sY[ni * 33 + ci];
    }
}

// Gather (R12-proven shape): 32 nodes/block, 4 per warp, i4 loop; group-parallel
// edge consume; pad-36 vectorized projection (mode 0); folded readout (mode 1).
__global__ void __launch_bounds__(256)
k_gather(int outB, const float* __restrict__ gatW, const float* __restrict__ gatb,
         const int* __restrict__ batch, float* __restrict__ out,
         int l, int N, int mode) {
    __shared__ __align__(16) float sGatW[HC * 36];
    __shared__ __align__(16) float4 sW[8][32];
    __shared__ int sS[8][32];
    __shared__ __align__(16) float sOut[32][132];
    __shared__ float sGatB[HC];

    int tid = threadIdx.x;
    int wid = tid >> 5, lane = tid & 31;
    if (mode == 0) {
        for (int m = tid; m < HC * NC; m += 256) {
            int r = m >> 5, c = m & 31;
            sGatW[r * 36 + c] = gatW[l * HC * NC + m];
        }
        if (tid < HC) sGatB[tid] = gatb[l * HC + tid];
    } else {
        for (int m = tid; m < OUTC * HC; m += 256) sGatW[m] = g_rF[m];
        if (tid < OUTC) sGatB[tid] = g_rc[tid];
    }
    __syncthreads();

    int hd = lane >> 3, q = lane & 7;
    int grp = lane >> 3;
    const float* __restrict__ ybase = g_y;

#pragma unroll 1
    for (int i4 = 0; i4 < 4; i4++) {
        int nl = wid * 4 + i4;
        int gw = blockIdx.x * 32 + nl;
        bool valid = (gw < N);
        int gws = valid ? gw : 0;

        int cnt = valid ? g_deg[gws] : 0;
        const int* __restrict__ lst = &g_pad[gws * CAP];
        float4 ad4 = make_float4(0.f, 0.f, 0.f, 0.f);
        float4 asSelf = make_float4(0.f, 0.f, 0.f, 0.f);
        if (valid) {
            ad4 = *reinterpret_cast<const float4*>(&g_ad[gws * NHD]);
            asSelf = *reinterpret_cast<const float4*>(&g_as[gws * NHD]);
        }
        float4 wself;
        wself.x = lrelu_exp(asSelf.x + ad4.x);
        wself.y = lrelu_exp(asSelf.y + ad4.y);
        wself.z = lrelu_exp(asSelf.z + ad4.z);
        wself.w = lrelu_exp(asSelf.w + ad4.w);

        float4 accH0 = make_float4(0.f, 0.f, 0.f, 0.f);
        float4 accH1 = make_float4(0.f, 0.f, 0.f, 0.f);
        float4 accH2 = make_float4(0.f, 0.f, 0.f, 0.f);
        float4 accH3 = make_float4(0.f, 0.f, 0.f, 0.f);
        float4 wsum4 = make_float4(0.f, 0.f, 0.f, 0.f);

        for (int base = 0; base < cnt; base += 32) {
            int c2 = min(32, cnt - base);
            int s_l = 0;
            float4 w4 = make_float4(0.f, 0.f, 0.f, 0.f);
            if (lane < c2) {
                s_l = lst[base + lane];
                const float4 as4 = *reinterpret_cast<const float4*>(&g_as[s_l * NHD]);
                w4.x = lrelu_exp(as4.x + ad4.x);
                w4.y = lrelu_exp(as4.y + ad4.y);
                w4.z = lrelu_exp(as4.z + ad4.z);
                w4.w = lrelu_exp(as4.w + ad4.w);
            }
            wsum4.x += w4.x; wsum4.y += w4.y; wsum4.z += w4.z; wsum4.w += w4.w;
            sS[wid][lane] = s_l;
            sW[wid][lane] = w4;
            __syncwarp();

            int j = grp;
            for (; j + 4 < c2; j += 8) {
                int sA = sS[wid][j], sB = sS[wid][j + 4];
                float4 weA = sW[wid][j], weB = sW[wid][j + 4];
                const float4 yA = *reinterpret_cast<const float4*>(&ybase[sA * NC + q * 4]);
                const float4 yB = *reinterpret_cast<const float4*>(&ybase[sB * NC + q * 4]);
                accH0.x = fmaf(weA.x, yA.x, accH0.x); accH0.y = fmaf(weA.x, yA.y, accH0.y);
                accH0.z = fmaf(weA.x, yA.z, accH0.z); accH0.w = fmaf(weA.x, yA.w, accH0.w);
                accH1.x = fmaf(weA.y, yA.x, accH1.x); accH1.y = fmaf(weA.y, yA.y, accH1.y);
                accH1.z = fmaf(weA.y, yA.z, accH1.z); accH1.w = fmaf(weA.y, yA.w, accH1.w);
                accH2.x = fmaf(weA.z, yA.x, accH2.x); accH2.y = fmaf(weA.z, yA.y, accH2.y);
                accH2.z = fmaf(weA.z, yA.z, accH2.z); accH2.w = fmaf(weA.z, yA.w, accH2.w);
                accH3.x = fmaf(weA.w, yA.x, accH3.x); accH3.y = fmaf(weA.w, yA.y, accH3.y);
                accH3.z = fmaf(weA.w, yA.z, accH3.z); accH3.w = fmaf(weA.w, yA.w, accH3.w);
                accH0.x = fmaf(weB.x, yB.x, accH0.x); accH0.y = fmaf(weB.x, yB.y, accH0.y);
                accH0.z = fmaf(weB.x, yB.z, accH0.z); accH0.w = fmaf(weB.x, yB.w, accH0.w);
                accH1.x = fmaf(weB.y, yB.x, accH1.x); accH1.y = fmaf(weB.y, yB.y, accH1.y);
                accH1.z = fmaf(weB.y, yB.z, accH1.z); accH1.w = fmaf(weB.y, yB.w, accH1.w);
                accH2.x = fmaf(weB.z, yB.x, accH2.x); accH2.y = fmaf(weB.z, yB.y, accH2.y);
                accH2.z = fmaf(weB.z, yB.z, accH2.z); accH2.w = fmaf(weB.z, yB.w, accH2.w);
                accH3.x = fmaf(weB.w, yB.x, accH3.x); accH3.y = fmaf(weB.w, yB.y, accH3.y);
                accH3.z = fmaf(weB.w, yB.z, accH3.z); accH3.w = fmaf(weB.w, yB.w, accH3.w);
            }
            if (j < c2) {
                int sA = sS[wid][j];
                float4 weA = sW[wid][j];
                const float4 yA = *reinterpret_cast<const float4*>(&ybase[sA * NC + q * 4]);
                accH0.x = fmaf(weA.x, yA.x, accH0.x); accH0.y = fmaf(weA.x, yA.y, accH0.y);
                accH0.z = fmaf(weA.x, yA.z, accH0.z); accH0.w = fmaf(weA.x, yA.w, accH0.w);
                accH1.x = fmaf(weA.y, yA.x, accH1.x); accH1.y = fmaf(weA.y, yA.y, accH1.y);
                accH1.z = fmaf(weA.y, yA.z, accH1.z); accH1.w = fmaf(weA.y, yA.w, accH1.w);
                accH2.x = fmaf(weA.z, yA.x, accH2.x); accH2.y = fmaf(weA.z, yA.y, accH2.y);
                accH2.z = fmaf(weA.z, yA.z, accH2.z); accH2.w = fmaf(weA.z, yA.w, accH2.w);
                accH3.x = fmaf(weA.w, yA.x, accH3.x); accH3.y = fmaf(weA.w, yA.y, accH3.y);
                accH3.z = fmaf(weA.w, yA.z, accH3.z); accH3.w = fmaf(weA.w, yA.w, accH3.w);
            }
            __syncwarp();
        }

#pragma unroll
        for (int off = 8; off <= 16; off <<= 1) {
            accH0.x += __shfl_xor_sync(0xffffffffu, accH0.x, off);
            accH0.y += __shfl_xor_sync(0xffffffffu, accH0.y, off);
            accH0.z += __shfl_xor_sync(0xffffffffu, accH0.z, off);
            accH0.w += __shfl_xor_sync(0xffffffffu, accH0.w, off);
            accH1.x += __shfl_xor_sync(0xffffffffu, accH1.x, off);
            accH1.y += __shfl_xor_sync(0xffffffffu, accH1.y, off);
            accH1.z += __shfl_xor_sync(0xffffffffu, accH1.z, off);
            accH1.w += __shfl_xor_sync(0xffffffffu, accH1.w, off);
            accH2.x += __shfl_xor_sync(0xffffffffu, accH2.x, off);
            accH2.y += __shfl_xor_sync(0xffffffffu, accH2.y, off);
            accH2.z += __shfl_xor_sync(0xffffffffu, accH2.z, off);
            accH2.w += __shfl_xor_sync(0xffffffffu, accH2.w, off);
            accH3.x += __shfl_xor_sync(0xffffffffu, accH3.x, off);
            accH3.y += __shfl_xor_sync(0xffffffffu, accH3.y, off);
            accH3.z += __shfl_xor_sync(0xffffffffu, accH3.z, off);
            accH3.w += __shfl_xor_sync(0xffffffffu, accH3.w, off);
        }
        float4 acc = (hd == 0) ? accH0 : (hd == 1) ? accH1 : (hd == 2) ? accH2 : accH3;

#pragma unroll
        for (int off = 16; off; off >>= 1) {
            wsum4.x += __shfl_xor_sync(0xffffffffu, wsum4.x, off);
            wsum4.y += __shfl_xor_sync(0xffffffffu, wsum4.y, off);
            wsum4.z += __shfl_xor_sync(0xffffffffu, wsum4.z, off);
            wsum4.w += __shfl_xor_sync(0xffffffffu, wsum4.w, off);
        }
        wsum4.x += wself.x; wsum4.y += wself.y; wsum4.z += wself.z; wsum4.w += wself.w;
        float wsh = (hd == 0) ? wself.x : (hd == 1) ? wself.y : (hd == 2) ? wself.z : wself.w;
        const float4 ys = *reinterpret_cast<const float4*>(&ybase[gws * NC + q * 4]);
        acc.x = fmaf(wsh, ys.x, acc.x); acc.y = fmaf(wsh, ys.y, acc.y);
        acc.z = fmaf(wsh, ys.z, acc.z); acc.w = fmaf(wsh, ys.w, acc.w);
        float wsumh = (hd == 0) ? wsum4.x : (hd == 1) ? wsum4.y : (hd == 2) ? wsum4.z : wsum4.w;
        float inv = 1.f / (wsumh + 1e-16f);
        acc.x *= inv; acc.y *= inv; acc.z *= inv; acc.w *= inv;

        if (mode == 0) {
            *reinterpret_cast<float4*>(&sOut[nl][lane * 4]) = acc;
            __syncwarp();

            float a[4];
#pragma unroll
            for (int i = 0; i < 4; i++) {
                int o = lane + 32 * i;
                float v = sGatB[o];
                const float4* aggh4 = reinterpret_cast<const float4*>(&sOut[nl][i * 32]);
                const float4* w4p = reinterpret_cast<const float4*>(&sGatW[o * 36]);
#pragma unroll
                for (int j = 0; j < 8; j++) {
                    float4 ag = aggh4[j];
                    float4 w = w4p[j];
                    v = fmaf(ag.x, w.x, v);
                    v = fmaf(ag.y, w.y, v);
                    v = fmaf(ag.z, w.z, v);
                    v = fmaf(ag.w, w.w, v);
                }
                a[i] = valid ? v : 0.f;
            }
            __syncwarp();
#pragma unroll
            for (int i = 0; i < 4; i++) sOut[nl][lane + 32 * i] = a[i];
        } else if (valid) {
            int g = batch[gw];
#pragma unroll
            for (int o = 0; o < OUTC; o++) {
                const float4 rf = *reinterpret_cast<const float4*>(&sGatW[o * HC + lane * 4]);
                float p = acc.x * rf.x + acc.y * rf.y + acc.z * rf.z + acc.w * rf.w;
#pragma unroll
                for (int off = 16; off; off >>= 1)
                    p += __shfl_xor_sync(0xffffffffu, p, off);
                if (lane == o) atomicAdd(&out[g * OUTC + o], p + sGatB[o]);
            }
        }
    }

    if (mode == 0) {
        __syncthreads();
        if (tid < HC) {
            float s = 0.f, s2 = 0.f;
#pragma unroll
            for (int w = 0; w < 32; w++) {
                float v = sOut[w][tid];
                s += v; s2 += v * v;
            }
            atomicAdd(&g_sumL[l + 1][tid], s);
            atomicAdd(&g_sqL[l + 1][tid], s2);
        }
        // channel-major feature write: 32 consecutive nodes = 128 B per channel sector
        float* ob = bufPtr(outB);
        int node = tid & 31;
        int gw2 = blockIdx.x * 32 + node;
        if (gw2 < N) {
            int cb = tid >> 5;
#pragma unroll
            for (int p = 0; p < 16; p++) {
                int cc = cb * 16 + p;
                ob[cc * NP + gw2] = sOut[node][cc];
            }
        }
    }
}

// ---------------- launch ----------------
extern "C" void kernel_launch(void* const* d_in, const int* in_sizes, int n_in,
                              void* d_out, int out_size) {
    const int*   xidx  = (const int*)d_in[0];
    const int*   ei    = (const int*)d_in[1];
    const int*   batch = (const int*)d_in[2];
    const float* embed = (const float*)d_in[3];
    const float* bng   = (const float*)d_in[4];
    const float* bnb   = (const float*)d_in[5];
    const float* linW  = (const float*)d_in[6];
    const float* linb  = (const float*)d_in[7];
    const float* gatW  = (const float*)d_in[8];
    const float* attS  = (const float*)d_in[9];
    const float* attD  = (const float*)d_in[10];
    const float* gatb  = (const float*)d_in[11];
    const float* rW    = (const float*)d_in[12];
    const float* rb    = (const float*)d_in[13];
    float* out = (float*)d_out;

    int N = in_sizes[0];
    int E = in_sizes[1] / 2;
    int nInit = (N + 255) / 256;
    int nA = (N + 63) / 64;
    int nB = (E + 255) / 256;

    k_init<<<nInit + NL + 1, 256>>>(out, out_size, N, nInit, gatW, attS, attD, gatb, rW, rb);
    k_embed_scatter<<<nA + nB, 256>>>(xidx, embed, ei, N, E, nA);

    for (int l = 0; l < NL; l++) {
        int inB = l & 1;
        int outB = inB ^ 1;
        int mode = (l == NL - 1) ? 1 : 0;
        k_prep<<<1, 128>>>(l, linW, linb, bng, bnb, N);
        k_node<<<(N + 127) / 128, 128>>>(inB, l, N);
        k_gather<<<(N + 31) / 32, 256>>>(outB, gatW, gatb, batch, out, l, N, mode);
    }
}

// round 15
// speedup vs baseline: 1.3506x; 1.0349x over previous
#include <cuda_runtime.h>

#define NN     50000
#define NP     50048
#define EE     800000
#define NHD    4
#define NC     32
#define HC     128
#define NL     3
#define OUTC   10
#define CAP    96
#define BN_EPS 1e-5f

// ---------------- static device scratch ----------------
__device__ __align__(16) float g_buf0[HC * NP];     // channel-major
__device__ __align__(16) float g_buf1[HC * NP];
__device__ __align__(16) float g_y[NN * NC];        // row-major
__device__ __align__(16) float g_as[NN * NHD];
__device__ __align__(16) float g_ad[NN * NHD];
__device__ float g_sumL[NL][HC];
__device__ float g_sqL[NL][HC];
__device__ float g_attF[NL][2][HC];                 // static per-layer folds
__device__ __align__(16) float g_rF[OUTC * HC];
__device__ float g_rc[OUTC];
__device__ int   g_deg[NN];
__device__ int   g_pad[NN * CAP];

__device__ __forceinline__ float* bufPtr(int b) { return b ? g_buf1 : g_buf0; }

__device__ __forceinline__ float lrelu_exp(float z) {
    z = (z > 0.f) ? z : 0.2f * z;
    return __expf(z);
}

// ---------------- kernels ----------------

// init + ALL static (BN-independent) weight folds, block-range split.
__global__ void __launch_bounds__(256)
k_init(float* __restrict__ out, int out_n, int N, int nInit,
       const float* __restrict__ gatW, const float* __restrict__ attS,
       const float* __restrict__ attD, const float* __restrict__ gatb,
       const float* __restrict__ rW, const float* __restrict__ rb) {
    int b = blockIdx.x;
    int tid = threadIdx.x;
    if (b < nInit) {
        int gid = b * 256 + tid;
        if (gid < N) g_deg[gid] = 0;
        if (gid < NL * HC) { (&g_sumL[0][0])[gid] = 0.f; (&g_sqL[0][0])[gid] = 0.f; }
        if (gid < out_n) out[gid] = 0.f;
    } else if (b < nInit + NL) {
        int l = b - nInit;
        if (tid < HC) {
            int hd = tid >> 5, cc = tid & 31;
            float a = 0.f, d = 0.f;
            for (int j = 0; j < 32; j++) {
                int r = hd * 32 + j;
                float w = __ldg(&gatW[l * HC * NC + r * NC + cc]);
                a = fmaf(w, __ldg(&attS[l * HC + r]), a);
                d = fmaf(w, __ldg(&attD[l * HC + r]), d);
            }
            g_attF[l][0][tid] = a;
            g_attF[l][1][tid] = d;
        }
    } else {
        int l = NL - 1;
        if (tid < HC) {
            int i = tid >> 5, cp = tid & 31;
#pragma unroll
            for (int o = 0; o < OUTC; o++) {
                float v = 0.f;
                for (int j = 0; j < 32; j++) {
                    int k = i * 32 + j;
                    v = fmaf(__ldg(&rW[o * HC + k]),
                             __ldg(&gatW[l * HC * NC + k * NC + cp]), v);
                }
                g_rF[o * HC + tid] = v;
            }
        }
        if (tid >= 128 && tid < 128 + OUTC) {
            int o = tid - 128;
            float v = rb[o];
            for (int k = 0; k < HC; k++)
                v = fmaf(__ldg(&rW[o * HC + k]), __ldg(&gatb[l * HC + k]), v);
            g_rc[o] = v;
        }
    }
}

// [0,nA): embed gather (channel-major) + layer-0 BN stats.  [nA,...): padded-CSR scatter.
__global__ void __launch_bounds__(256)
k_embed_scatter(const int* __restrict__ xidx, const float* __restrict__ embed,
                const int* __restrict__ ei, int N, int E, int nA) {
    int tid = threadIdx.x;
    if ((int)blockIdx.x < nA) {
        __shared__ float sS[2][HC], sQ[2][HC];
        __shared__ float sT[64][129];
        int c = tid & 127, sub = tid >> 7;
        int r0 = blockIdx.x * 64;
        float s = 0.f, s2 = 0.f;
#pragma unroll 4
        for (int it = 0; it < 32; it++) {
            int rl = sub + it * 2;
            int r = r0 + rl;
            float v = 0.f;
            if (r < N) {
                v = embed[xidx[r] * HC + c];
                s += v; s2 += v * v;
            }
            sT[rl][c] = v;
        }
        sS[sub][c] = s; sQ[sub][c] = s2;
        __syncthreads();
        if (tid < HC) {
            atomicAdd(&g_sumL[0][tid], sS[0][tid] + sS[1][tid]);
            atomicAdd(&g_sqL[0][tid], sQ[0][tid] + sQ[1][tid]);
        }
        int node = tid & 63;
        int cb = tid >> 6;
        int r = r0 + node;
        if (r < N) {
#pragma unroll
            for (int p = 0; p < 32; p++) {
                int cc = cb * 32 + p;
                g_buf0[cc * NP + r] = sT[node][cc];
            }
        }
    } else {
        int gid = (blockIdx.x - nA) * 256 + tid;
        if (gid < E) {
            int s = ei[gid], d = ei[E + gid];
            int pos = atomicAdd(&g_deg[d], 1);
            g_pad[d * CAP + pos] = s;
        }
    }
}

// Per-node GEMM, fused BN/weight fold, k-split: 256 threads, 128 nodes/block.
// half 0 handles k in [0,64), half 1 k in [64,128). Partials combined via SMEM.
__global__ void __launch_bounds__(256)
k_node(int inB, int l,
       const float* __restrict__ linW, const float* __restrict__ linb,
       const float* __restrict__ bng, const float* __restrict__ bnb, int N) {
    __shared__ __align__(16) float sLinT[HC * 36];   // folded [k][c], pad-36 (144B rows)
    __shared__ float sScale[HC], sShift[HC];
    __shared__ float sAs[HC], sAd[HC], sConst[NC];
    __shared__ float sRed[256];
    __shared__ __align__(16) float sPart[128 * 33];  // half-1 partials / y staging

    int tid = threadIdx.x;
    int half = tid >> 7;         // 0 or 1
    int nd = tid & 127;

    if (tid < HC) {
        float invN = 1.0f / (float)N;
        float mean = g_sumL[l][tid] * invN;
        float var  = g_sqL[l][tid] * invN - mean * mean;
        float rstd = rsqrtf(var + BN_EPS);
        float sc = bng[l * HC + tid] * rstd;
        sScale[tid] = sc;
        sShift[tid] = bnb[l * HC + tid] - sc * mean;
        sAs[tid] = g_attF[l][0][tid];
        sAd[tid] = g_attF[l][1][tid];
    }
    __syncthreads();

    // fold linW -> sLinT[k*36 + c]; thread owns (k = tid>>1, 16 channels)
    {
        int k = tid >> 1, ch0 = (tid & 1) * 16;
        float sc = sScale[k];
#pragma unroll
        for (int c = 0; c < 16; c++)
            sLinT[k * 36 + ch0 + c] = __ldg(&linW[l * NC * HC + (ch0 + c) * HC + k]) * sc;
    }
    // const partials: tid = kseg*32 + c, kseg 0..7 covers 16 k each
    {
        int c = tid & 31, kseg = tid >> 5;
        float p = 0.f;
        int kb = kseg * 16;
#pragma unroll
        for (int k2 = 0; k2 < 16; k2++)
            p = fmaf(__ldg(&linW[l * NC * HC + c * HC + kb + k2]), sShift[kb + k2], p);
        sRed[tid] = p;
    }
    __syncthreads();
    if (tid < NC) {
        float cst = linb[l * NC + tid];
#pragma unroll
        for (int seg = 0; seg < 8; seg++) cst += sRed[seg * 32 + tid];
        sConst[tid] = cst;
    }

    int n0 = blockIdx.x * 128;
    int n = n0 + nd;
    const float* __restrict__ xb = bufPtr(inB);

    float y[NC];
#pragma unroll
    for (int c = 0; c < NC; c++) y[c] = 0.f;

    int k0 = half * 64;
#pragma unroll 2
    for (int kb = k0; kb < k0 + 64; kb += 8) {
        float xv[8];
#pragma unroll
        for (int u = 0; u < 8; u++) xv[u] = xb[(kb + u) * NP + n];
#pragma unroll
        for (int u = 0; u < 8; u++) {
            const float4* wr = reinterpret_cast<const float4*>(&sLinT[(kb + u) * 36]);
            float xu = xv[u];
#pragma unroll
            for (int q = 0; q < 8; q++) {
                float4 w = wr[q];
                y[4 * q]     = fmaf(xu, w.x, y[4 * q]);
                y[4 * q + 1] = fmaf(xu, w.y, y[4 * q + 1]);
                y[4 * q + 2] = fmaf(xu, w.z, y[4 * q + 2]);
                y[4 * q + 3] = fmaf(xu, w.w, y[4 * q + 3]);
            }
        }
    }

    __syncthreads();   // sLinT no longer needed; sPart safe to write
    if (half == 1) {
#pragma unroll
        for (int c = 0; c < NC; c++) sPart[nd * 33 + c] = y[c];
    }
    __syncthreads();

    if (half == 0) {
        const float* pp = &sPart[nd * 33];
#pragma unroll
        for (int c = 0; c < NC; c++)
            y[c] = fmaxf(y[c] + pp[c] + sConst[c], 0.f);

        if (n < N) {
            float as[NHD] = {0.f, 0.f, 0.f, 0.f}, ad[NHD] = {0.f, 0.f, 0.f, 0.f};
#pragma unroll
            for (int hd = 0; hd < NHD; hd++) {
#pragma unroll
                for (int c = 0; c < NC; c++) {
                    as[hd] = fmaf(y[c], sAs[hd * 32 + c], as[hd]);
                    ad[hd] = fmaf(y[c], sAd[hd * 32 + c], ad[hd]);
                }
            }
            *reinterpret_cast<float4*>(&g_as[n * NHD]) = make_float4(as[0], as[1], as[2], as[3]);
            *reinterpret_cast<float4*>(&g_ad[n * NHD]) = make_float4(ad[0], ad[1], ad[2], ad[3]);
        }
    }
    __syncthreads();
    if (half == 0) {
#pragma unroll
        for (int c = 0; c < NC; c++) sPart[nd * 33 + c] = y[c];
    }
    __syncthreads();
    // coalesced row-major g_y write: 4096 floats, 16 per thread
#pragma unroll
    for (int j = 0; j < 16; j++) {
        int i = tid + j * 256;
        int ni = i >> 5, ci = i & 31;
        int nn = n0 + ni;
        if (nn < N) g_y[nn * NC + ci] = sPart[ni * 33 + ci];
    }
}

// Gather (R14-proven): 32 nodes/block, 4 per warp, i4 loop; group-parallel
// edge consume; pad-36 vectorized projection (mode 0); folded readout (mode 1).
__global__ void __launch_bounds__(256)
k_gather(int outB, const float* __restrict__ gatW, const float* __restrict__ gatb,
         const int* __restrict__ batch, float* __restrict__ out,
         int l, int N, int mode) {
    __shared__ __align__(16) float sGatW[HC * 36];
    __shared__ __align__(16) float4 sW[8][32];
    __shared__ int sS[8][32];
    __shared__ __align__(16) float sOut[32][132];
    __shared__ float sGatB[HC];

    int tid = threadIdx.x;
    int wid = tid >> 5, lane = tid & 31;
    if (mode == 0) {
        for (int m = tid; m < HC * NC; m += 256) {
            int r = m >> 5, c = m & 31;
            sGatW[r * 36 + c] = gatW[l * HC * NC + m];
        }
        if (tid < HC) sGatB[tid] = gatb[l * HC + tid];
    } else {
        for (int m = tid; m < OUTC * HC; m += 256) sGatW[m] = g_rF[m];
        if (tid < OUTC) sGatB[tid] = g_rc[tid];
    }
    __syncthreads();

    int hd = lane >> 3, q = lane & 7;
    int grp = lane >> 3;
    const float* __restrict__ ybase = g_y;

#pragma unroll 1
    for (int i4 = 0; i4 < 4; i4++) {
        int nl = wid * 4 + i4;
        int gw = blockIdx.x * 32 + nl;
        bool valid = (gw < N);
        int gws = valid ? gw : 0;

        int cnt = valid ? g_deg[gws] : 0;
        const int* __restrict__ lst = &g_pad[gws * CAP];
        float4 ad4 = make_float4(0.f, 0.f, 0.f, 0.f);
        float4 asSelf = make_float4(0.f, 0.f, 0.f, 0.f);
        if (valid) {
            ad4 = *reinterpret_cast<const float4*>(&g_ad[gws * NHD]);
            asSelf = *reinterpret_cast<const float4*>(&g_as[gws * NHD]);
        }
        float4 wself;
        wself.x = lrelu_exp(asSelf.x + ad4.x);
        wself.y = lrelu_exp(asSelf.y + ad4.y);
        wself.z = lrelu_exp(asSelf.z + ad4.z);
        wself.w = lrelu_exp(asSelf.w + ad4.w);

        float4 accH0 = make_float4(0.f, 0.f, 0.f, 0.f);
        float4 accH1 = make_float4(0.f, 0.f, 0.f, 0.f);
        float4 accH2 = make_float4(0.f, 0.f, 0.f, 0.f);
        float4 accH3 = make_float4(0.f, 0.f, 0.f, 0.f);
        float4 wsum4 = make_float4(0.f, 0.f, 0.f, 0.f);

        for (int base = 0; base < cnt; base += 32) {
            int c2 = min(32, cnt - base);
            int s_l = 0;
            float4 w4 = make_float4(0.f, 0.f, 0.f, 0.f);
            if (lane < c2) {
                s_l = lst[base + lane];
                const float4 as4 = *reinterpret_cast<const float4*>(&g_as[s_l * NHD]);
                w4.x = lrelu_exp(as4.x + ad4.x);
                w4.y = lrelu_exp(as4.y + ad4.y);
                w4.z = lrelu_exp(as4.z + ad4.z);
                w4.w = lrelu_exp(as4.w + ad4.w);
            }
            wsum4.x += w4.x; wsum4.y += w4.y; wsum4.z += w4.z; wsum4.w += w4.w;
            sS[wid][lane] = s_l;
            sW[wid][lane] = w4;
            __syncwarp();

            int j = grp;
            for (; j + 4 < c2; j += 8) {
                int sA = sS[wid][j], sB = sS[wid][j + 4];
                float4 weA = sW[wid][j], weB = sW[wid][j + 4];
                const float4 yA = *reinterpret_cast<const float4*>(&ybase[sA * NC + q * 4]);
                const float4 yB = *reinterpret_cast<const float4*>(&ybase[sB * NC + q * 4]);
                accH0.x = fmaf(weA.x, yA.x, accH0.x); accH0.y = fmaf(weA.x, yA.y, accH0.y);
                accH0.z = fmaf(weA.x, yA.z, accH0.z); accH0.w = fmaf(weA.x, yA.w, accH0.w);
                accH1.x = fmaf(weA.y, yA.x, accH1.x); accH1.y = fmaf(weA.y, yA.y, accH1.y);
                accH1.z = fmaf(weA.y, yA.z, accH1.z); accH1.w = fmaf(weA.y, yA.w, accH1.w);
                accH2.x = fmaf(weA.z, yA.x, accH2.x); accH2.y = fmaf(weA.z, yA.y, accH2.y);
                accH2.z = fmaf(weA.z, yA.z, accH2.z); accH2.w = fmaf(weA.z, yA.w, accH2.w);
                accH3.x = fmaf(weA.w, yA.x, accH3.x); accH3.y = fmaf(weA.w, yA.y, accH3.y);
                accH3.z = fmaf(weA.w, yA.z, accH3.z); accH3.w = fmaf(weA.w, yA.w, accH3.w);
                accH0.x = fmaf(weB.x, yB.x, accH0.x); accH0.y = fmaf(weB.x, yB.y, accH0.y);
                accH0.z = fmaf(weB.x, yB.z, accH0.z); accH0.w = fmaf(weB.x, yB.w, accH0.w);
                accH1.x = fmaf(weB.y, yB.x, accH1.x); accH1.y = fmaf(weB.y, yB.y, accH1.y);
                accH1.z = fmaf(weB.y, yB.z, accH1.z); accH1.w = fmaf(weB.y, yB.w, accH1.w);
                accH2.x = fmaf(weB.z, yB.x, accH2.x); accH2.y = fmaf(weB.z, yB.y, accH2.y);
                accH2.z = fmaf(weB.z, yB.z, accH2.z); accH2.w = fmaf(weB.z, yB.w, accH2.w);
                accH3.x = fmaf(weB.w, yB.x, accH3.x); accH3.y = fmaf(weB.w, yB.y, accH3.y);
                accH3.z = fmaf(weB.w, yB.z, accH3.z); accH3.w = fmaf(weB.w, yB.w, accH3.w);
            }
            if (j < c2) {
                int sA = sS[wid][j];
                float4 weA = sW[wid][j];
                const float4 yA = *reinterpret_cast<const float4*>(&ybase[sA * NC + q * 4]);
                accH0.x = fmaf(weA.x, yA.x, accH0.x); accH0.y = fmaf(weA.x, yA.y, accH0.y);
                accH0.z = fmaf(weA.x, yA.z, accH0.z); accH0.w = fmaf(weA.x, yA.w, accH0.w);
                accH1.x = fmaf(weA.y, yA.x, accH1.x); accH1.y = fmaf(weA.y, yA.y, accH1.y);
                accH1.z = fmaf(weA.y, yA.z, accH1.z); accH1.w = fmaf(weA.y, yA.w, accH1.w);
                accH2.x = fmaf(weA.z, yA.x, accH2.x); accH2.y = fmaf(weA.z, yA.y, accH2.y);
                accH2.z = fmaf(weA.z, yA.z, accH2.z); accH2.w = fmaf(weA.z, yA.w, accH2.w);
                accH3.x = fmaf(weA.w, yA.x, accH3.x); accH3.y = fmaf(weA.w, yA.y, accH3.y);
                accH3.z = fmaf(weA.w, yA.z, accH3.z); accH3.w = fmaf(weA.w, yA.w, accH3.w);
            }
            __syncwarp();
        }

#pragma unroll
        for (int off = 8; off <= 16; off <<= 1) {
            accH0.x += __shfl_xor_sync(0xffffffffu, accH0.x, off);
            accH0.y += __shfl_xor_sync(0xffffffffu, accH0.y, off);
            accH0.z += __shfl_xor_sync(0xffffffffu, accH0.z, off);
            accH0.w += __shfl_xor_sync(0xffffffffu, accH0.w, off);
            accH1.x += __shfl_xor_sync(0xffffffffu, accH1.x, off);
            accH1.y += __shfl_xor_sync(0xffffffffu, accH1.y, off);
            accH1.z += __shfl_xor_sync(0xffffffffu, accH1.z, off);
            accH1.w += __shfl_xor_sync(0xffffffffu, accH1.w, off);
            accH2.x += __shfl_xor_sync(0xffffffffu, accH2.x, off);
            accH2.y += __shfl_xor_sync(0xffffffffu, accH2.y, off);
            accH2.z += __shfl_xor_sync(0xffffffffu, accH2.z, off);
            accH2.w += __shfl_xor_sync(0xffffffffu, accH2.w, off);
            accH3.x += __shfl_xor_sync(0xffffffffu, accH3.x, off);
            accH3.y += __shfl_xor_sync(0xffffffffu, accH3.y, off);
            accH3.z += __shfl_xor_sync(0xffffffffu, accH3.z, off);
            accH3.w += __shfl_xor_sync(0xffffffffu, accH3.w, off);
        }
        float4 acc = (hd == 0) ? accH0 : (hd == 1) ? accH1 : (hd == 2) ? accH2 : accH3;

#pragma unroll
        for (int off = 16; off; off >>= 1) {
            wsum4.x += __shfl_xor_sync(0xffffffffu, wsum4.x, off);
            wsum4.y += __shfl_xor_sync(0xffffffffu, wsum4.y, off);
            wsum4.z += __shfl_xor_sync(0xffffffffu, wsum4.z, off);
            wsum4.w += __shfl_xor_sync(0xffffffffu, wsum4.w, off);
        }
        wsum4.x += wself.x; wsum4.y += wself.y; wsum4.z += wself.z; wsum4.w += wself.w;
        float wsh = (hd == 0) ? wself.x : (hd == 1) ? wself.y : (hd == 2) ? wself.z : wself.w;
        const float4 ys = *reinterpret_cast<const float4*>(&ybase[gws * NC + q * 4]);
        acc.x = fmaf(wsh, ys.x, acc.x); acc.y = fmaf(wsh, ys.y, acc.y);
        acc.z = fmaf(wsh, ys.z, acc.z); acc.w = fmaf(wsh, ys.w, acc.w);
        float wsumh = (hd == 0) ? wsum4.x : (hd == 1) ? wsum4.y : (hd == 2) ? wsum4.z : wsum4.w;
        float inv = 1.f / (wsumh + 1e-16f);
        acc.x *= inv; acc.y *= inv; acc.z *= inv; acc.w *= inv;

        if (mode == 0) {
            *reinterpret_cast<float4*>(&sOut[nl][lane * 4]) = acc;
            __syncwarp();

            float a[4];
#pragma unroll
            for (int i = 0; i < 4; i++) {
                int o = lane + 32 * i;
                float v = sGatB[o];
                const float4* aggh4 = reinterpret_cast<const float4*>(&sOut[nl][i * 32]);
                const float4* w4p = reinterpret_cast<const float4*>(&sGatW[o * 36]);
#pragma unroll
                for (int j = 0; j < 8; j++) {
                    float4 ag = aggh4[j];
                    float4 w = w4p[j];
                    v = fmaf(ag.x, w.x, v);
                    v = fmaf(ag.y, w.y, v);
                    v = fmaf(ag.z, w.z, v);
                    v = fmaf(ag.w, w.w, v);
                }
                a[i] = valid ? v : 0.f;
            }
            __syncwarp();
#pragma unroll
            for (int i = 0; i < 4; i++) sOut[nl][lane + 32 * i] = a[i];
        } else if (valid) {
            int g = batch[gw];
#pragma unroll
            for (int o = 0; o < OUTC; o++) {
                const float4 rf = *reinterpret_cast<const float4*>(&sGatW[o * HC + lane * 4]);
                float p = acc.x * rf.x + acc.y * rf.y + acc.z * rf.z + acc.w * rf.w;
#pragma unroll
                for (int off = 16; off; off >>= 1)
                    p += __shfl_xor_sync(0xffffffffu, p, off);
                if (lane == o) atomicAdd(&out[g * OUTC + o], p + sGatB[o]);
            }
        }
    }

    if (mode == 0) {
        __syncthreads();
        if (tid < HC) {
            float s = 0.f, s2 = 0.f;
#pragma unroll
            for (int w = 0; w < 32; w++) {
                float v = sOut[w][tid];
                s += v; s2 += v * v;
            }
            atomicAdd(&g_sumL[l + 1][tid], s);
            atomicAdd(&g_sqL[l + 1][tid], s2);
        }
        float* ob = bufPtr(outB);
        int node = tid & 31;
        int gw2 = blockIdx.x * 32 + node;
        if (gw2 < N) {
            int cb = tid >> 5;
#pragma unroll
            for (int p = 0; p < 16; p++) {
                int cc = cb * 16 + p;
                ob[cc * NP + gw2] = sOut[node][cc];
            }
        }
    }
}

// ---------------- launch ----------------
extern "C" void kernel_launch(void* const* d_in, const int* in_sizes, int n_in,
                              void* d_out, int out_size) {
    const int*   xidx  = (const int*)d_in[0];
    const int*   ei    = (const int*)d_in[1];
    const int*   batch = (const int*)d_in[2];
    const float* embed = (const float*)d_in[3];
    const float* bng   = (const float*)d_in[4];
    const float* bnb   = (const float*)d_in[5];
    const float* linW  = (const float*)d_in[6];
    const float* linb  = (const float*)d_in[7];
    const float* gatW  = (const float*)d_in[8];
    const float* attS  = (const float*)d_in[9];
    const float* attD  = (const float*)d_in[10];
    const float* gatb  = (const float*)d_in[11];
    const float* rW    = (const float*)d_in[12];
    const float* rb    = (const float*)d_in[13];
    float* out = (float*)d_out;

    int N = in_sizes[0];
    int E = in_sizes[1] / 2;
    int nInit = (N + 255) / 256;
    int nA = (N + 63) / 64;
    int nB = (E + 255) / 256;

    k_init<<<nInit + NL + 1, 256>>>(out, out_size, N, nInit, gatW, attS, attD, gatb, rW, rb);
    k_embed_scatter<<<nA + nB, 256>>>(xidx, embed, ei, N, E, nA);

    for (int l = 0; l < NL; l++) {
        int inB = l & 1;
        int outB = inB ^ 1;
        int mode = (l == NL - 1) ? 1 : 0;
        k_node<<<(N + 127) / 128, 256>>>(inB, l, linW, linb, bng, bnb, N);
        k_gather<<<(N + 31) / 32, 256>>>(outB, gatW, gatb, batch, out, l, N, mode);
    }
}

// round 16
// speedup vs baseline: 1.4371x; 1.0640x over previous
#include <cuda_runtime.h>

#define NN     50000
#define NP     50048
#define EE     800000
#define NHD    4
#define NC     32
#define HC     128
#define NL     3
#define OUTC   10
#define CAP    96
#define BN_EPS 1e-5f

// ---------------- static device scratch ----------------
__device__ __align__(16) float g_buf0[HC * NP];     // channel-major
__device__ __align__(16) float g_buf1[HC * NP];
__device__ __align__(16) float g_y[NN * NC];        // row-major
__device__ __align__(16) float g_as[NN * NHD];
__device__ __align__(16) float g_ad[NN * NHD];
__device__ float g_sumL[NL][HC];
__device__ float g_sqL[NL][HC];
__device__ float g_attF[NL][2][HC];
__device__ __align__(16) float g_rF[OUTC * HC];
__device__ float g_rc[OUTC];
__device__ int   g_deg[NN];
__device__ int   g_pad[NN * CAP];

__device__ __forceinline__ float* bufPtr(int b) { return b ? g_buf1 : g_buf0; }

__device__ __forceinline__ float lrelu_exp(float z) {
    z = (z > 0.f) ? z : 0.2f * z;
    return __expf(z);
}

__device__ __forceinline__ float4 f4add(float4 a, float4 b) {
    return make_float4(a.x + b.x, a.y + b.y, a.z + b.z, a.w + b.w);
}
__device__ __forceinline__ float4 shfl_xor_f4(float4 v, int m) {
    v.x = __shfl_xor_sync(0xffffffffu, v.x, m);
    v.y = __shfl_xor_sync(0xffffffffu, v.y, m);
    v.z = __shfl_xor_sync(0xffffffffu, v.z, m);
    v.w = __shfl_xor_sync(0xffffffffu, v.w, m);
    return v;
}

// ---------------- kernels ----------------

__global__ void __launch_bounds__(256)
k_init(float* __restrict__ out, int out_n, int N, int nInit,
       const float* __restrict__ gatW, const float* __restrict__ attS,
       const float* __restrict__ attD, const float* __restrict__ gatb,
       const float* __restrict__ rW, const float* __restrict__ rb) {
    int b = blockIdx.x;
    int tid = threadIdx.x;
    if (b < nInit) {
        int gid = b * 256 + tid;
        if (gid < N) g_deg[gid] = 0;
        if (gid < NL * HC) { (&g_sumL[0][0])[gid] = 0.f; (&g_sqL[0][0])[gid] = 0.f; }
        if (gid < out_n) out[gid] = 0.f;
    } else if (b < nInit + NL) {
        int l = b - nInit;
        if (tid < HC) {
            int hd = tid >> 5, cc = tid & 31;
            float a = 0.f, d = 0.f;
            for (int j = 0; j < 32; j++) {
                int r = hd * 32 + j;
                float w = __ldg(&gatW[l * HC * NC + r * NC + cc]);
                a = fmaf(w, __ldg(&attS[l * HC + r]), a);
                d = fmaf(w, __ldg(&attD[l * HC + r]), d);
            }
            g_attF[l][0][tid] = a;
            g_attF[l][1][tid] = d;
        }
    } else {
        int l = NL - 1;
        if (tid < HC) {
            int i = tid >> 5, cp = tid & 31;
#pragma unroll
            for (int o = 0; o < OUTC; o++) {
                float v = 0.f;
                for (int j = 0; j < 32; j++) {
                    int k = i * 32 + j;
                    v = fmaf(__ldg(&rW[o * HC + k]),
                             __ldg(&gatW[l * HC * NC + k * NC + cp]), v);
                }
                g_rF[o * HC + tid] = v;
            }
        }
        if (tid >= 128 && tid < 128 + OUTC) {
            int o = tid - 128;
            float v = rb[o];
            for (int k = 0; k < HC; k++)
                v = fmaf(__ldg(&rW[o * HC + k]), __ldg(&gatb[l * HC + k]), v);
            g_rc[o] = v;
        }
    }
}

__global__ void __launch_bounds__(256)
k_embed_scatter(const int* __restrict__ xidx, const float* __restrict__ embed,
                const int* __restrict__ ei, int N, int E, int nA) {
    int tid = threadIdx.x;
    if ((int)blockIdx.x < nA) {
        __shared__ float sS[2][HC], sQ[2][HC];
        __shared__ float sT[64][129];
        int c = tid & 127, sub = tid >> 7;
        int r0 = blockIdx.x * 64;
        float s = 0.f, s2 = 0.f;
#pragma unroll 4
        for (int it = 0; it < 32; it++) {
            int rl = sub + it * 2;
            int r = r0 + rl;
            float v = 0.f;
            if (r < N) {
                v = embed[xidx[r] * HC + c];
                s += v; s2 += v * v;
            }
            sT[rl][c] = v;
        }
        sS[sub][c] = s; sQ[sub][c] = s2;
        __syncthreads();
        if (tid < HC) {
            atomicAdd(&g_sumL[0][tid], sS[0][tid] + sS[1][tid]);
            atomicAdd(&g_sqL[0][tid], sQ[0][tid] + sQ[1][tid]);
        }
        int node = tid & 63;
        int cb = tid >> 6;
        int r = r0 + node;
        if (r < N) {
#pragma unroll
            for (int p = 0; p < 32; p++) {
                int cc = cb * 32 + p;
                g_buf0[cc * NP + r] = sT[node][cc];
            }
        }
    } else {
        int gid = (blockIdx.x - nA) * 256 + tid;
        if (gid < E) {
            int s = ei[gid], d = ei[E + gid];
            int pos = atomicAdd(&g_deg[d], 1);
            g_pad[d * CAP + pos] = s;
        }
    }
}

// Per-node GEMM, fused BN/weight fold, k-split (R15-proven).
__global__ void __launch_bounds__(256)
k_node(int inB, int l,
       const float* __restrict__ linW, const float* __restrict__ linb,
       const float* __restrict__ bng, const float* __restrict__ bnb, int N) {
    __shared__ __align__(16) float sLinT[HC * 36];
    __shared__ float sScale[HC], sShift[HC];
    __shared__ float sAs[HC], sAd[HC], sConst[NC];
    __shared__ float sRed[256];
    __shared__ __align__(16) float sPart[128 * 33];

    int tid = threadIdx.x;
    int half = tid >> 7;
    int nd = tid & 127;

    if (tid < HC) {
        float invN = 1.0f / (float)N;
        float mean = g_sumL[l][tid] * invN;
        float var  = g_sqL[l][tid] * invN - mean * mean;
        float rstd = rsqrtf(var + BN_EPS);
        float sc = bng[l * HC + tid] * rstd;
        sScale[tid] = sc;
        sShift[tid] = bnb[l * HC + tid] - sc * mean;
        sAs[tid] = g_attF[l][0][tid];
        sAd[tid] = g_attF[l][1][tid];
    }
    __syncthreads();

    {
        int k = tid >> 1, ch0 = (tid & 1) * 16;
        float sc = sScale[k];
#pragma unroll
        for (int c = 0; c < 16; c++)
            sLinT[k * 36 + ch0 + c] = __ldg(&linW[l * NC * HC + (ch0 + c) * HC + k]) * sc;
    }
    {
        int c = tid & 31, kseg = tid >> 5;
        float p = 0.f;
        int kb = kseg * 16;
#pragma unroll
        for (int k2 = 0; k2 < 16; k2++)
            p = fmaf(__ldg(&linW[l * NC * HC + c * HC + kb + k2]), sShift[kb + k2], p);
        sRed[tid] = p;
    }
    __syncthreads();
    if (tid < NC) {
        float cst = linb[l * NC + tid];
#pragma unroll
        for (int seg = 0; seg < 8; seg++) cst += sRed[seg * 32 + tid];
        sConst[tid] = cst;
    }

    int n0 = blockIdx.x * 128;
    int n = n0 + nd;
    const float* __restrict__ xb = bufPtr(inB);

    float y[NC];
#pragma unroll
    for (int c = 0; c < NC; c++) y[c] = 0.f;

    int k0 = half * 64;
#pragma unroll 2
    for (int kb = k0; kb < k0 + 64; kb += 8) {
        float xv[8];
#pragma unroll
        for (int u = 0; u < 8; u++) xv[u] = xb[(kb + u) * NP + n];
#pragma unroll
        for (int u = 0; u < 8; u++) {
            const float4* wr = reinterpret_cast<const float4*>(&sLinT[(kb + u) * 36]);
            float xu = xv[u];
#pragma unroll
            for (int q = 0; q < 8; q++) {
                float4 w = wr[q];
                y[4 * q]     = fmaf(xu, w.x, y[4 * q]);
                y[4 * q + 1] = fmaf(xu, w.y, y[4 * q + 1]);
                y[4 * q + 2] = fmaf(xu, w.z, y[4 * q + 2]);
                y[4 * q + 3] = fmaf(xu, w.w, y[4 * q + 3]);
            }
        }
    }

    __syncthreads();
    if (half == 1) {
#pragma unroll
        for (int c = 0; c < NC; c++) sPart[nd * 33 + c] = y[c];
    }
    __syncthreads();

    if (half == 0) {
        const float* pp = &sPart[nd * 33];
#pragma unroll
        for (int c = 0; c < NC; c++)
            y[c] = fmaxf(y[c] + pp[c] + sConst[c], 0.f);

        if (n < N) {
            float as[NHD] = {0.f, 0.f, 0.f, 0.f}, ad[NHD] = {0.f, 0.f, 0.f, 0.f};
#pragma unroll
            for (int hd = 0; hd < NHD; hd++) {
#pragma unroll
                for (int c = 0; c < NC; c++) {
                    as[hd] = fmaf(y[c], sAs[hd * 32 + c], as[hd]);
                    ad[hd] = fmaf(y[c], sAd[hd * 32 + c], ad[hd]);
                }
            }
            *reinterpret_cast<float4*>(&g_as[n * NHD]) = make_float4(as[0], as[1], as[2], as[3]);
            *reinterpret_cast<float4*>(&g_ad[n * NHD]) = make_float4(ad[0], ad[1], ad[2], ad[3]);
        }
    }
    __syncthreads();
    if (half == 0) {
#pragma unroll
        for (int c = 0; c < NC; c++) sPart[nd * 33 + c] = y[c];
    }
    __syncthreads();
#pragma unroll
    for (int j = 0; j < 16; j++) {
        int i = tid + j * 256;
        int ni = i >> 5, ci = i & 31;
        int nn = n0 + ni;
        if (nn < N) g_y[nn * NC + ci] = sPart[ni * 33 + ci];
    }
}

// Gather: 32 nodes/block, 4/warp; group-parallel edge consume; select-based
// transposed head folds; forced 4 blocks/SM.
__global__ void __launch_bounds__(256, 4)
k_gather(int outB, const float* __restrict__ gatW, const float* __restrict__ gatb,
         const int* __restrict__ batch, float* __restrict__ out,
         int l, int N, int mode) {
    __shared__ __align__(16) float sGatW[HC * 36];
    __shared__ __align__(16) float4 sW[8][32];
    __shared__ int sS[8][32];
    __shared__ __align__(16) float sOut[32][132];
    __shared__ float sGatB[HC];

    int tid = threadIdx.x;
    int wid = tid >> 5, lane = tid & 31;
    if (mode == 0) {
        for (int m = tid; m < HC * NC; m += 256) {
            int r = m >> 5, c = m & 31;
            sGatW[r * 36 + c] = gatW[l * HC * NC + m];
        }
        if (tid < HC) sGatB[tid] = gatb[l * HC + tid];
    } else {
        for (int m = tid; m < OUTC * HC; m += 256) sGatW[m] = g_rF[m];
        if (tid < OUTC) sGatB[tid] = g_rc[tid];
    }
    __syncthreads();

    int hd = lane >> 3, q = lane & 7;
    int b0 = hd & 1, b1 = hd >> 1;
    const float* __restrict__ ybase = g_y;

#pragma unroll 1
    for (int i4 = 0; i4 < 4; i4++) {
        int nl = wid * 4 + i4;
        int gw = blockIdx.x * 32 + nl;
        bool valid = (gw < N);
        int gws = valid ? gw : 0;

        int cnt = valid ? g_deg[gws] : 0;
        const int* __restrict__ lst = &g_pad[gws * CAP];
        float4 ad4 = make_float4(0.f, 0.f, 0.f, 0.f);
        if (valid) ad4 = *reinterpret_cast<const float4*>(&g_ad[gws * NHD]);

        // self-edge: computed up front so its inputs die before the loop
        float4 wself;
        {
            float4 asSelf = make_float4(0.f, 0.f, 0.f, 0.f);
            if (valid) asSelf = *reinterpret_cast<const float4*>(&g_as[gws * NHD]);
            wself.x = lrelu_exp(asSelf.x + ad4.x);
            wself.y = lrelu_exp(asSelf.y + ad4.y);
            wself.z = lrelu_exp(asSelf.z + ad4.z);
            wself.w = lrelu_exp(asSelf.w + ad4.w);
        }

        float4 accH0 = make_float4(0.f, 0.f, 0.f, 0.f);
        float4 accH1 = make_float4(0.f, 0.f, 0.f, 0.f);
        float4 accH2 = make_float4(0.f, 0.f, 0.f, 0.f);
        float4 accH3 = make_float4(0.f, 0.f, 0.f, 0.f);
        float4 wsum4 = make_float4(0.f, 0.f, 0.f, 0.f);

        for (int base = 0; base < cnt; base += 32) {
            int c2 = min(32, cnt - base);
            int s_l = 0;
            float4 w4 = make_float4(0.f, 0.f, 0.f, 0.f);
            if (lane < c2) {
                s_l = lst[base + lane];
                const float4 as4 = *reinterpret_cast<const float4*>(&g_as[s_l * NHD]);
                w4.x = lrelu_exp(as4.x + ad4.x);
                w4.y = lrelu_exp(as4.y + ad4.y);
                w4.z = lrelu_exp(as4.z + ad4.z);
                w4.w = lrelu_exp(as4.w + ad4.w);
            }
            wsum4.x += w4.x; wsum4.y += w4.y; wsum4.z += w4.z; wsum4.w += w4.w;
            sS[wid][lane] = s_l;
            sW[wid][lane] = w4;
            __syncwarp();

            int j = hd;  // group id == hd
            for (; j + 4 < c2; j += 8) {
                int sA = sS[wid][j], sB = sS[wid][j + 4];
                float4 weA = sW[wid][j], weB = sW[wid][j + 4];
                const float4 yA = *reinterpret_cast<const float4*>(&ybase[sA * NC + q * 4]);
                const float4 yB = *reinterpret_cast<const float4*>(&ybase[sB * NC + q * 4]);
                accH0.x = fmaf(weA.x, yA.x, accH0.x); accH0.y = fmaf(weA.x, yA.y, accH0.y);
                accH0.z = fmaf(weA.x, yA.z, accH0.z); accH0.w = fmaf(weA.x, yA.w, accH0.w);
                accH1.x = fmaf(weA.y, yA.x, accH1.x); accH1.y = fmaf(weA.y, yA.y, accH1.y);
                accH1.z = fmaf(weA.y, yA.z, accH1.z); accH1.w = fmaf(weA.y, yA.w, accH1.w);
                accH2.x = fmaf(weA.z, yA.x, accH2.x); accH2.y = fmaf(weA.z, yA.y, accH2.y);
                accH2.z = fmaf(weA.z, yA.z, accH2.z); accH2.w = fmaf(weA.z, yA.w, accH2.w);
                accH3.x = fmaf(weA.w, yA.x, accH3.x); accH3.y = fmaf(weA.w, yA.y, accH3.y);
                accH3.z = fmaf(weA.w, yA.z, accH3.z); accH3.w = fmaf(weA.w, yA.w, accH3.w);
                accH0.x = fmaf(weB.x, yB.x, accH0.x); accH0.y = fmaf(weB.x, yB.y, accH0.y);
                accH0.z = fmaf(weB.x, yB.z, accH0.z); accH0.w = fmaf(weB.x, yB.w, accH0.w);
                accH1.x = fmaf(weB.y, yB.x, accH1.x); accH1.y = fmaf(weB.y, yB.y, accH1.y);
                accH1.z = fmaf(weB.y, yB.z, accH1.z); accH1.w = fmaf(weB.y, yB.w, accH1.w);
                accH2.x = fmaf(weB.z, yB.x, accH2.x); accH2.y = fmaf(weB.z, yB.y, accH2.y);
                accH2.z = fmaf(weB.z, yB.z, accH2.z); accH2.w = fmaf(weB.z, yB.w, accH2.w);
                accH3.x = fmaf(weB.w, yB.x, accH3.x); accH3.y = fmaf(weB.w, yB.y, accH3.y);
                accH3.z = fmaf(weB.w, yB.z, accH3.z); accH3.w = fmaf(weB.w, yB.w, accH3.w);
            }
            if (j < c2) {
                int sA = sS[wid][j];
                float4 weA = sW[wid][j];
                const float4 yA = *reinterpret_cast<const float4*>(&ybase[sA * NC + q * 4]);
                accH0.x = fmaf(weA.x, yA.x, accH0.x); accH0.y = fmaf(weA.x, yA.y, accH0.y);
                accH0.z = fmaf(weA.x, yA.z, accH0.z); accH0.w = fmaf(weA.x, yA.w, accH0.w);
                accH1.x = fmaf(weA.y, yA.x, accH1.x); accH1.y = fmaf(weA.y, yA.y, accH1.y);
                accH1.z = fmaf(weA.y, yA.z, accH1.z); accH1.w = fmaf(weA.y, yA.w, accH1.w);
                accH2.x = fmaf(weA.z, yA.x, accH2.x); accH2.y = fmaf(weA.z, yA.y, accH2.y);
                accH2.z = fmaf(weA.z, yA.z, accH2.z); accH2.w = fmaf(weA.z, yA.w, accH2.w);
                accH3.x = fmaf(weA.w, yA.x, accH3.x); accH3.y = fmaf(weA.w, yA.y, accH3.y);
                accH3.z = fmaf(weA.w, yA.z, accH3.z); accH3.w = fmaf(weA.w, yA.w, accH3.w);
            }
            __syncwarp();
        }

        // select-based transposed fold: acc = sum over groups of accH[own hd]
        float4 keep1 = b1 ? (b0 ? accH3 : accH2) : (b0 ? accH1 : accH0);  // accH[hd]
        float4 send1 = b1 ? (b0 ? accH2 : accH3) : (b0 ? accH0 : accH1);  // accH[hd^1]
        float4 keep2 = b1 ? (b0 ? accH1 : accH0) : (b0 ? accH3 : accH2);  // accH[hd^2]
        float4 send2 = b1 ? (b0 ? accH0 : accH1) : (b0 ? accH2 : accH3);  // accH[hd^3]
        float4 Pown = f4add(keep1, shfl_xor_f4(send1, 8));
        float4 Palt = f4add(keep2, shfl_xor_f4(send2, 8));
        float4 acc = f4add(Pown, shfl_xor_f4(Palt, 16));

        // wsum: full-warp reduce of 4 heads, then self
#pragma unroll
        for (int off = 16; off; off >>= 1) {
            wsum4.x += __shfl_xor_sync(0xffffffffu, wsum4.x, off);
            wsum4.y += __shfl_xor_sync(0xffffffffu, wsum4.y, off);
            wsum4.z += __shfl_xor_sync(0xffffffffu, wsum4.z, off);
            wsum4.w += __shfl_xor_sync(0xffffffffu, wsum4.w, off);
        }
        wsum4.x += wself.x; wsum4.y += wself.y; wsum4.z += wself.z; wsum4.w += wself.w;
        float wsh = (hd == 0) ? wself.x : (hd == 1) ? wself.y : (hd == 2) ? wself.z : wself.w;
        const float4 ys = *reinterpret_cast<const float4*>(&ybase[gws * NC + q * 4]);
        acc.x = fmaf(wsh, ys.x, acc.x); acc.y = fmaf(wsh, ys.y, acc.y);
        acc.z = fmaf(wsh, ys.z, acc.z); acc.w = fmaf(wsh, ys.w, acc.w);
        float wsumh = (hd == 0) ? wsum4.x : (hd == 1) ? wsum4.y : (hd == 2) ? wsum4.z : wsum4.w;
        float inv = 1.f / (wsumh + 1e-16f);
        acc.x *= inv; acc.y *= inv; acc.z *= inv; acc.w *= inv;

        if (mode == 0) {
            *reinterpret_cast<float4*>(&sOut[nl][lane * 4]) = acc;
            __syncwarp();

            float a[4];
#pragma unroll
            for (int i = 0; i < 4; i++) {
                int o = lane + 32 * i;
                float v = sGatB[o];
                const float4* aggh4 = reinterpret_cast<const float4*>(&sOut[nl][i * 32]);
                const float4* w4p = reinterpret_cast<const float4*>(&sGatW[o * 36]);
#pragma unroll
                for (int j = 0; j < 8; j++) {
                    float4 ag = aggh4[j];
                    float4 w = w4p[j];
                    v = fmaf(ag.x, w.x, v);
                    v = fmaf(ag.y, w.y, v);
                    v = fmaf(ag.z, w.z, v);
                    v = fmaf(ag.w, w.w, v);
                }
                a[i] = valid ? v : 0.f;
            }
            __syncwarp();
#pragma unroll
            for (int i = 0; i < 4; i++) sOut[nl][lane + 32 * i] = a[i];
        } else if (valid) {
            int g = batch[gw];
#pragma unroll
            for (int o = 0; o < OUTC; o++) {
                const float4 rf = *reinterpret_cast<const float4*>(&sGatW[o * HC + lane * 4]);
                float p = acc.x * rf.x + acc.y * rf.y + acc.z * rf.z + acc.w * rf.w;
#pragma unroll
                for (int off = 16; off; off >>= 1)
                    p += __shfl_xor_sync(0xffffffffu, p, off);
                if (lane == o) atomicAdd(&out[g * OUTC + o], p + sGatB[o]);
            }
        }
    }

    if (mode == 0) {
        __syncthreads();
        if (tid < HC) {
            float s = 0.f, s2 = 0.f;
#pragma unroll
            for (int w = 0; w < 32; w++) {
                float v = sOut[w][tid];
                s += v; s2 += v * v;
            }
            atomicAdd(&g_sumL[l + 1][tid], s);
            atomicAdd(&g_sqL[l + 1][tid], s2);
        }
        float* ob = bufPtr(outB);
        int node = tid & 31;
        int gw2 = blockIdx.x * 32 + node;
        if (gw2 < N) {
            int cb = tid >> 5;
#pragma unroll
            for (int p = 0; p < 16; p++) {
                int cc = cb * 16 + p;
                ob[cc * NP + gw2] = sOut[node][cc];
            }
        }
    }
}

// ---------------- launch ----------------
extern "C" void kernel_launch(void* const* d_in, const int* in_sizes, int n_in,
                              void* d_out, int out_size) {
    const int*   xidx  = (const int*)d_in[0];
    const int*   ei    = (const int*)d_in[1];
    const int*   batch = (const int*)d_in[2];
    const float* embed = (const float*)d_in[3];
    const float* bng   = (const float*)d_in[4];
    const float* bnb   = (const float*)d_in[5];
    const float* linW  = (const float*)d_in[6];
    const float* linb  = (const float*)d_in[7];
    const float* gatW  = (const float*)d_in[8];
    const float* attS  = (const float*)d_in[9];
    const float* attD  = (const float*)d_in[10];
    const float* gatb  = (const float*)d_in[11];
    const float* rW    = (const float*)d_in[12];
    const float* rb    = (const float*)d_in[13];
    float* out = (float*)d_out;

    int N = in_sizes[0];
    int E = in_sizes[1] / 2;
    int nInit = (N + 255) / 256;
    int nA = (N + 63) / 64;
    int nB = (E + 255) / 256;

    k_init<<<nInit + NL + 1, 256>>>(out, out_size, N, nInit, gatW, attS, attD, gatb, rW, rb);
    k_embed_scatter<<<nA + nB, 256>>>(xidx, embed, ei, N, E, nA);

    for (int l = 0; l < NL; l++) {
        int inB = l & 1;
        int outB = inB ^ 1;
        int mode = (l == NL - 1) ? 1 : 0;
        k_node<<<(N + 127) / 128, 256>>>(inB, l, linW, linb, bng, bnb, N);
        k_gather<<<(N + 31) / 32, 256>>>(outB, gatW, gatb, batch, out, l, N, mode);
    }
}

// round 17
// speedup vs baseline: 1.5843x; 1.1024x over previous
#include <cuda_runtime.h>

#define NN     50000
#define NP     50048
#define EE     800000
#define NHD    4
#define NC     32
#define HC     128
#define NL     3
#define OUTC   10
#define CAP    96
#define BN_EPS 1e-5f

// ---------------- static device scratch ----------------
__device__ __align__(16) float g_buf0[HC * NP];     // channel-major
__device__ __align__(16) float g_buf1[HC * NP];
__device__ __align__(16) float g_y[NN * NC];        // row-major
__device__ __align__(16) float g_as[NN * NHD];
__device__ __align__(16) float g_ad[NN * NHD];
__device__ float g_sumL[NL][HC];
__device__ float g_sqL[NL][HC];
__device__ float g_attF[NL][2][HC];
__device__ __align__(16) float g_rF[OUTC * HC];
__device__ float g_rc[OUTC];
__device__ int   g_deg[NN];
__device__ int   g_pad[NN * CAP];

__device__ __forceinline__ float* bufPtr(int b) { return b ? g_buf1 : g_buf0; }

__device__ __forceinline__ float lrelu_exp(float z) {
    z = (z > 0.f) ? z : 0.2f * z;
    return __expf(z);
}

__device__ __forceinline__ float4 f4add(float4 a, float4 b) {
    return make_float4(a.x + b.x, a.y + b.y, a.z + b.z, a.w + b.w);
}
__device__ __forceinline__ float4 shfl_xor_f4(float4 v, int m) {
    v.x = __shfl_xor_sync(0xffffffffu, v.x, m);
    v.y = __shfl_xor_sync(0xffffffffu, v.y, m);
    v.z = __shfl_xor_sync(0xffffffffu, v.z, m);
    v.w = __shfl_xor_sync(0xffffffffu, v.w, m);
    return v;
}

// ---------------- kernels ----------------

__global__ void __launch_bounds__(256)
k_init(float* __restrict__ out, int out_n, int N, int nInit,
       const float* __restrict__ gatW, const float* __restrict__ attS,
       const float* __restrict__ attD, const float* __restrict__ gatb,
       const float* __restrict__ rW, const float* __restrict__ rb) {
    int b = blockIdx.x;
    int tid = threadIdx.x;
    if (b < nInit) {
        int gid = b * 256 + tid;
        if (gid < N) g_deg[gid] = 0;
        if (gid < NL * HC) { (&g_sumL[0][0])[gid] = 0.f; (&g_sqL[0][0])[gid] = 0.f; }
        if (gid < out_n) out[gid] = 0.f;
    } else if (b < nInit + NL) {
        int l = b - nInit;
        if (tid < HC) {
            int hd = tid >> 5, cc = tid & 31;
            float a = 0.f, d = 0.f;
            for (int j = 0; j < 32; j++) {
                int r = hd * 32 + j;
                float w = __ldg(&gatW[l * HC * NC + r * NC + cc]);
                a = fmaf(w, __ldg(&attS[l * HC + r]), a);
                d = fmaf(w, __ldg(&attD[l * HC + r]), d);
            }
            g_attF[l][0][tid] = a;
            g_attF[l][1][tid] = d;
        }
    } else {
        int l = NL - 1;
        if (tid < HC) {
            int i = tid >> 5, cp = tid & 31;
#pragma unroll
            for (int o = 0; o < OUTC; o++) {
                float v = 0.f;
                for (int j = 0; j < 32; j++) {
                    int k = i * 32 + j;
                    v = fmaf(__ldg(&rW[o * HC + k]),
                             __ldg(&gatW[l * HC * NC + k * NC + cp]), v);
                }
                g_rF[o * HC + tid] = v;
            }
        }
        if (tid >= 128 && tid < 128 + OUTC) {
            int o = tid - 128;
            float v = rb[o];
            for (int k = 0; k < HC; k++)
                v = fmaf(__ldg(&rW[o * HC + k]), __ldg(&gatb[l * HC + k]), v);
            g_rc[o] = v;
        }
    }
}

__global__ void __launch_bounds__(256)
k_embed_scatter(const int* __restrict__ xidx, const float* __restrict__ embed,
                const int* __restrict__ ei, int N, int E, int nA) {
    int tid = threadIdx.x;
    if ((int)blockIdx.x < nA) {
        __shared__ float sS[2][HC], sQ[2][HC];
        __shared__ float sT[64][129];
        int c = tid & 127, sub = tid >> 7;
        int r0 = blockIdx.x * 64;
        float s = 0.f, s2 = 0.f;
#pragma unroll 4
        for (int it = 0; it < 32; it++) {
            int rl = sub + it * 2;
            int r = r0 + rl;
            float v = 0.f;
            if (r < N) {
                v = embed[xidx[r] * HC + c];
                s += v; s2 += v * v;
            }
            sT[rl][c] = v;
        }
        sS[sub][c] = s; sQ[sub][c] = s2;
        __syncthreads();
        if (tid < HC) {
            atomicAdd(&g_sumL[0][tid], sS[0][tid] + sS[1][tid]);
            atomicAdd(&g_sqL[0][tid], sQ[0][tid] + sQ[1][tid]);
        }
        int node = tid & 63;
        int cb = tid >> 6;
        int r = r0 + node;
        if (r < N) {
#pragma unroll
            for (int p = 0; p < 32; p++) {
                int cc = cb * 32 + p;
                g_buf0[cc * NP + r] = sT[node][cc];
            }
        }
    } else {
        int gid = (blockIdx.x - nA) * 256 + tid;
        if (gid < E) {
            int s = ei[gid], d = ei[E + gid];
            int pos = atomicAdd(&g_deg[d], 1);
            g_pad[d * CAP + pos] = s;
        }
    }
}

// Per-node GEMM, fused BN/weight fold, k-split (R15-proven).
__global__ void __launch_bounds__(256)
k_node(int inB, int l,
       const float* __restrict__ linW, const float* __restrict__ linb,
       const float* __restrict__ bng, const float* __restrict__ bnb, int N) {
    __shared__ __align__(16) float sLinT[HC * 36];
    __shared__ float sScale[HC], sShift[HC];
    __shared__ float sAs[HC], sAd[HC], sConst[NC];
    __shared__ float sRed[256];
    __shared__ __align__(16) float sPart[128 * 33];

    int tid = threadIdx.x;
    int half = tid >> 7;
    int nd = tid & 127;

    if (tid < HC) {
        float invN = 1.0f / (float)N;
        float mean = g_sumL[l][tid] * invN;
        float var  = g_sqL[l][tid] * invN - mean * mean;
        float rstd = rsqrtf(var + BN_EPS);
        float sc = bng[l * HC + tid] * rstd;
        sScale[tid] = sc;
        sShift[tid] = bnb[l * HC + tid] - sc * mean;
        sAs[tid] = g_attF[l][0][tid];
        sAd[tid] = g_attF[l][1][tid];
    }
    __syncthreads();

    {
        int k = tid >> 1, ch0 = (tid & 1) * 16;
        float sc = sScale[k];
#pragma unroll
        for (int c = 0; c < 16; c++)
            sLinT[k * 36 + ch0 + c] = __ldg(&linW[l * NC * HC + (ch0 + c) * HC + k]) * sc;
    }
    {
        int c = tid & 31, kseg = tid >> 5;
        float p = 0.f;
        int kb = kseg * 16;
#pragma unroll
        for (int k2 = 0; k2 < 16; k2++)
            p = fmaf(__ldg(&linW[l * NC * HC + c * HC + kb + k2]), sShift[kb + k2], p);
        sRed[tid] = p;
    }
    __syncthreads();
    if (tid < NC) {
        float cst = linb[l * NC + tid];
#pragma unroll
        for (int seg = 0; seg < 8; seg++) cst += sRed[seg * 32 + tid];
        sConst[tid] = cst;
    }

    int n0 = blockIdx.x * 128;
    int n = n0 + nd;
    const float* __restrict__ xb = bufPtr(inB);

    float y[NC];
#pragma unroll
    for (int c = 0; c < NC; c++) y[c] = 0.f;

    int k0 = half * 64;
#pragma unroll 2
    for (int kb = k0; kb < k0 + 64; kb += 8) {
        float xv[8];
#pragma unroll
        for (int u = 0; u < 8; u++) xv[u] = xb[(kb + u) * NP + n];
#pragma unroll
        for (int u = 0; u < 8; u++) {
            const float4* wr = reinterpret_cast<const float4*>(&sLinT[(kb + u) * 36]);
            float xu = xv[u];
#pragma unroll
            for (int q = 0; q < 8; q++) {
                float4 w = wr[q];
                y[4 * q]     = fmaf(xu, w.x, y[4 * q]);
                y[4 * q + 1] = fmaf(xu, w.y, y[4 * q + 1]);
                y[4 * q + 2] = fmaf(xu, w.z, y[4 * q + 2]);
                y[4 * q + 3] = fmaf(xu, w.w, y[4 * q + 3]);
            }
        }
    }

    __syncthreads();
    if (half == 1) {
#pragma unroll
        for (int c = 0; c < NC; c++) sPart[nd * 33 + c] = y[c];
    }
    __syncthreads();

    if (half == 0) {
        const float* pp = &sPart[nd * 33];
#pragma unroll
        for (int c = 0; c < NC; c++)
            y[c] = fmaxf(y[c] + pp[c] + sConst[c], 0.f);

        if (n < N) {
            float as[NHD] = {0.f, 0.f, 0.f, 0.f}, ad[NHD] = {0.f, 0.f, 0.f, 0.f};
#pragma unroll
            for (int hd = 0; hd < NHD; hd++) {
#pragma unroll
                for (int c = 0; c < NC; c++) {
                    as[hd] = fmaf(y[c], sAs[hd * 32 + c], as[hd]);
                    ad[hd] = fmaf(y[c], sAd[hd * 32 + c], ad[hd]);
                }
            }
            *reinterpret_cast<float4*>(&g_as[n * NHD]) = make_float4(as[0], as[1], as[2], as[3]);
            *reinterpret_cast<float4*>(&g_ad[n * NHD]) = make_float4(ad[0], ad[1], ad[2], ad[3]);
        }
    }
    __syncthreads();
    if (half == 0) {
#pragma unroll
        for (int c = 0; c < NC; c++) sPart[nd * 33 + c] = y[c];
    }
    __syncthreads();
#pragma unroll
    for (int j = 0; j < 16; j++) {
        int i = tid + j * 256;
        int ni = i >> 5, ci = i & 31;
        int nn = n0 + ni;
        if (nn < N) g_y[nn * NC + ci] = sPart[ni * 33 + ci];
    }
}

// Gather: 32 nodes/block, 4/warp; group-parallel edge consume; select-based
// transposed head folds; block-wide warp-uniform projection (mode 0).
#define AGS 133
__global__ void __launch_bounds__(256, 4)
k_gather(int outB, const float* __restrict__ gatW, const float* __restrict__ gatb,
         const int* __restrict__ batch, float* __restrict__ out,
         int l, int N, int mode) {
    __shared__ __align__(16) float sGatW[HC * 36];
    __shared__ __align__(16) float4 sW[8][32];
    __shared__ int sS[8][32];
    __shared__ __align__(16) float sAgg[32 * AGS];   // stride-133: conflict-free node-major
    __shared__ float sGatB[HC];

    int tid = threadIdx.x;
    int wid = tid >> 5, lane = tid & 31;
    if (mode == 0) {
        for (int m = tid; m < HC * NC; m += 256) {
            int r = m >> 5, c = m & 31;
            sGatW[r * 36 + c] = gatW[l * HC * NC + m];
        }
        if (tid < HC) sGatB[tid] = gatb[l * HC + tid];
    } else {
        for (int m = tid; m < OUTC * HC; m += 256) sGatW[m] = g_rF[m];
        if (tid < OUTC) sGatB[tid] = g_rc[tid];
    }
    __syncthreads();

    int hd = lane >> 3, q = lane & 7;
    int b0 = hd & 1, b1 = hd >> 1;
    const float* __restrict__ ybase = g_y;

#pragma unroll 1
    for (int i4 = 0; i4 < 4; i4++) {
        int nl = wid * 4 + i4;
        int gw = blockIdx.x * 32 + nl;
        bool valid = (gw < N);
        int gws = valid ? gw : 0;

        int cnt = valid ? g_deg[gws] : 0;
        const int* __restrict__ lst = &g_pad[gws * CAP];
        float4 ad4 = make_float4(0.f, 0.f, 0.f, 0.f);
        if (valid) ad4 = *reinterpret_cast<const float4*>(&g_ad[gws * NHD]);

        float4 wself;
        {
            float4 asSelf = make_float4(0.f, 0.f, 0.f, 0.f);
            if (valid) asSelf = *reinterpret_cast<const float4*>(&g_as[gws * NHD]);
            wself.x = lrelu_exp(asSelf.x + ad4.x);
            wself.y = lrelu_exp(asSelf.y + ad4.y);
            wself.z = lrelu_exp(asSelf.z + ad4.z);
            wself.w = lrelu_exp(asSelf.w + ad4.w);
        }

        float4 accH0 = make_float4(0.f, 0.f, 0.f, 0.f);
        float4 accH1 = make_float4(0.f, 0.f, 0.f, 0.f);
        float4 accH2 = make_float4(0.f, 0.f, 0.f, 0.f);
        float4 accH3 = make_float4(0.f, 0.f, 0.f, 0.f);
        float4 wsum4 = make_float4(0.f, 0.f, 0.f, 0.f);

        for (int base = 0; base < cnt; base += 32) {
            int c2 = min(32, cnt - base);
            int s_l = 0;
            float4 w4 = make_float4(0.f, 0.f, 0.f, 0.f);
            if (lane < c2) {
                s_l = lst[base + lane];
                const float4 as4 = *reinterpret_cast<const float4*>(&g_as[s_l * NHD]);
                w4.x = lrelu_exp(as4.x + ad4.x);
                w4.y = lrelu_exp(as4.y + ad4.y);
                w4.z = lrelu_exp(as4.z + ad4.z);
                w4.w = lrelu_exp(as4.w + ad4.w);
            }
            wsum4.x += w4.x; wsum4.y += w4.y; wsum4.z += w4.z; wsum4.w += w4.w;
            sS[wid][lane] = s_l;
            sW[wid][lane] = w4;
            __syncwarp();

            int j = hd;
            for (; j + 4 < c2; j += 8) {
                int sA = sS[wid][j], sB = sS[wid][j + 4];
                float4 weA = sW[wid][j], weB = sW[wid][j + 4];
                const float4 yA = *reinterpret_cast<const float4*>(&ybase[sA * NC + q * 4]);
                const float4 yB = *reinterpret_cast<const float4*>(&ybase[sB * NC + q * 4]);
                accH0.x = fmaf(weA.x, yA.x, accH0.x); accH0.y = fmaf(weA.x, yA.y, accH0.y);
                accH0.z = fmaf(weA.x, yA.z, accH0.z); accH0.w = fmaf(weA.x, yA.w, accH0.w);
                accH1.x = fmaf(weA.y, yA.x, accH1.x); accH1.y = fmaf(weA.y, yA.y, accH1.y);
                accH1.z = fmaf(weA.y, yA.z, accH1.z); accH1.w = fmaf(weA.y, yA.w, accH1.w);
                accH2.x = fmaf(weA.z, yA.x, accH2.x); accH2.y = fmaf(weA.z, yA.y, accH2.y);
                accH2.z = fmaf(weA.z, yA.z, accH2.z); accH2.w = fmaf(weA.z, yA.w, accH2.w);
                accH3.x = fmaf(weA.w, yA.x, accH3.x); accH3.y = fmaf(weA.w, yA.y, accH3.y);
                accH3.z = fmaf(weA.w, yA.z, accH3.z); accH3.w = fmaf(weA.w, yA.w, accH3.w);
                accH0.x = fmaf(weB.x, yB.x, accH0.x); accH0.y = fmaf(weB.x, yB.y, accH0.y);
                accH0.z = fmaf(weB.x, yB.z, accH0.z); accH0.w = fmaf(weB.x, yB.w, accH0.w);
                accH1.x = fmaf(weB.y, yB.x, accH1.x); accH1.y = fmaf(weB.y, yB.y, accH1.y);
                accH1.z = fmaf(weB.y, yB.z, accH1.z); accH1.w = fmaf(weB.y, yB.w, accH1.w);
                accH2.x = fmaf(weB.z, yB.x, accH2.x); accH2.y = fmaf(weB.z, yB.y, accH2.y);
                accH2.z = fmaf(weB.z, yB.z, accH2.z); accH2.w = fmaf(weB.z, yB.w, accH2.w);
                accH3.x = fmaf(weB.w, yB.x, accH3.x); accH3.y = fmaf(weB.w, yB.y, accH3.y);
                accH3.z = fmaf(weB.w, yB.z, accH3.z); accH3.w = fmaf(weB.w, yB.w, accH3.w);
            }
            if (j < c2) {
                int sA = sS[wid][j];
                float4 weA = sW[wid][j];
                const float4 yA = *reinterpret_cast<const float4*>(&ybase[sA * NC + q * 4]);
                accH0.x = fmaf(weA.x, yA.x, accH0.x); accH0.y = fmaf(weA.x, yA.y, accH0.y);
                accH0.z = fmaf(weA.x, yA.z, accH0.z); accH0.w = fmaf(weA.x, yA.w, accH0.w);
                accH1.x = fmaf(weA.y, yA.x, accH1.x); accH1.y = fmaf(weA.y, yA.y, accH1.y);
                accH1.z = fmaf(weA.y, yA.z, accH1.z); accH1.w = fmaf(weA.y, yA.w, accH1.w);
                accH2.x = fmaf(weA.z, yA.x, accH2.x); accH2.y = fmaf(weA.z, yA.y, accH2.y);
                accH2.z = fmaf(weA.z, yA.z, accH2.z); accH2.w = fmaf(weA.z, yA.w, accH2.w);
                accH3.x = fmaf(weA.w, yA.x, accH3.x); accH3.y = fmaf(weA.w, yA.y, accH3.y);
                accH3.z = fmaf(weA.w, yA.z, accH3.z); accH3.w = fmaf(weA.w, yA.w, accH3.w);
            }
            __syncwarp();
        }

        // select-based transposed fold: acc = sum over groups of accH[own hd]
        float4 keep1 = b1 ? (b0 ? accH3 : accH2) : (b0 ? accH1 : accH0);
        float4 send1 = b1 ? (b0 ? accH2 : accH3) : (b0 ? accH0 : accH1);
        float4 keep2 = b1 ? (b0 ? accH1 : accH0) : (b0 ? accH3 : accH2);
        float4 send2 = b1 ? (b0 ? accH0 : accH1) : (b0 ? accH2 : accH3);
        float4 Pown = f4add(keep1, shfl_xor_f4(send1, 8));
        float4 Palt = f4add(keep2, shfl_xor_f4(send2, 8));
        float4 acc = f4add(Pown, shfl_xor_f4(Palt, 16));

#pragma unroll
        for (int off = 16; off; off >>= 1) {
            wsum4.x += __shfl_xor_sync(0xffffffffu, wsum4.x, off);
            wsum4.y += __shfl_xor_sync(0xffffffffu, wsum4.y, off);
            wsum4.z += __shfl_xor_sync(0xffffffffu, wsum4.z, off);
            wsum4.w += __shfl_xor_sync(0xffffffffu, wsum4.w, off);
        }
        wsum4.x += wself.x; wsum4.y += wself.y; wsum4.z += wself.z; wsum4.w += wself.w;
        float wsh = (hd == 0) ? wself.x : (hd == 1) ? wself.y : (hd == 2) ? wself.z : wself.w;
        const float4 ys = *reinterpret_cast<const float4*>(&ybase[gws * NC + q * 4]);
        acc.x = fmaf(wsh, ys.x, acc.x); acc.y = fmaf(wsh, ys.y, acc.y);
        acc.z = fmaf(wsh, ys.z, acc.z); acc.w = fmaf(wsh, ys.w, acc.w);
        float wsumh = (hd == 0) ? wsum4.x : (hd == 1) ? wsum4.y : (hd == 2) ? wsum4.z : wsum4.w;
        float inv = 1.f / (wsumh + 1e-16f);
        acc.x *= inv; acc.y *= inv; acc.z *= inv; acc.w *= inv;

        if (mode == 0) {
            // stash normalized agg head-major at node-major stride-133 (scalar, low-conflict)
            int ab = nl * AGS + lane * 4;
            sAgg[ab]     = acc.x;
            sAgg[ab + 1] = acc.y;
            sAgg[ab + 2] = acc.z;
            sAgg[ab + 3] = acc.w;
        } else if (valid) {
            int g = batch[gw];
#pragma unroll
            for (int o = 0; o < OUTC; o++) {
                const float4 rf = *reinterpret_cast<const float4*>(&sGatW[o * HC + lane * 4]);
                float p = acc.x * rf.x + acc.y * rf.y + acc.z * rf.z + acc.w * rf.w;
#pragma unroll
                for (int off = 16; off; off >>= 1)
                    p += __shfl_xor_sync(0xffffffffu, p, off);
                if (lane == o) atomicAdd(&out[g * OUTC + o], p + sGatB[o]);
            }
        }
    }

    if (mode == 0) {
        __syncthreads();
        // Block-wide projection: warp w -> outputs [w*16, w*16+16); lane = node.
        // Weight reads warp-uniform (broadcast); agg reads conflict-free (stride 133).
        int node = lane;
        int gw2 = blockIdx.x * 32 + node;
        int og = wid;                 // 0..7
        int h = og >> 1;              // head of this warp's outputs
        int obase = og * 16;
        float aout[16];
#pragma unroll
        for (int hf = 0; hf < 2; hf++) {
            float a8[8];
#pragma unroll
            for (int k = 0; k < 8; k++) a8[k] = sGatB[obase + hf * 8 + k];
#pragma unroll
            for (int cc = 0; cc < 4; cc++) {
                float ag[8];
#pragma unroll
                for (int u = 0; u < 8; u++)
                    ag[u] = sAgg[node * AGS + h * 32 + cc * 8 + u];
#pragma unroll
                for (int k = 0; k < 8; k++) {
                    const float4* wp = reinterpret_cast<const float4*>(
                        &sGatW[(obase + hf * 8 + k) * 36 + cc * 8]);
                    float4 w0 = wp[0], w1 = wp[1];   // uniform -> broadcast
                    float v = a8[k];
                    v = fmaf(ag[0], w0.x, v); v = fmaf(ag[1], w0.y, v);
                    v = fmaf(ag[2], w0.z, v); v = fmaf(ag[3], w0.w, v);
                    v = fmaf(ag[4], w1.x, v); v = fmaf(ag[5], w1.y, v);
                    v = fmaf(ag[6], w1.z, v); v = fmaf(ag[7], w1.w, v);
                    a8[k] = v;
                }
            }
#pragma unroll
            for (int k = 0; k < 8; k++) aout[hf * 8 + k] = (gw2 < N) ? a8[k] : 0.f;
        }
        __syncthreads();
#pragma unroll
        for (int k = 0; k < 16; k++)
            sAgg[node * AGS + obase + k] = aout[k];   // bank = node*5+o: conflict-free
        __syncthreads();

        // next-layer BN stats
        if (tid < HC) {
            float s = 0.f, s2 = 0.f;
#pragma unroll
            for (int w = 0; w < 32; w++) {
                float v = sAgg[w * AGS + tid];
                s += v; s2 += v * v;
            }
            atomicAdd(&g_sumL[l + 1][tid], s);
            atomicAdd(&g_sqL[l + 1][tid], s2);
        }
        // channel-major feature write
        float* ob = bufPtr(outB);
        int nwr = tid & 31;
        int gww = blockIdx.x * 32 + nwr;
        if (gww < N) {
            int cb = tid >> 5;
#pragma unroll
            for (int p = 0; p < 16; p++) {
                int cc = cb * 16 + p;
                ob[cc * NP + gww] = sAgg[nwr * AGS + cc];
            }
        }
    }
}

// ---------------- launch ----------------
extern "C" void kernel_launch(void* const* d_in, const int* in_sizes, int n_in,
                              void* d_out, int out_size) {
    const int*   xidx  = (const int*)d_in[0];
    const int*   ei    = (const int*)d_in[1];
    const int*   batch = (const int*)d_in[2];
    const float* embed = (const float*)d_in[3];
    const float* bng   = (const float*)d_in[4];
    const float* bnb   = (const float*)d_in[5];
    const float* linW  = (const float*)d_in[6];
    const float* linb  = (const float*)d_in[7];
    const float* gatW  = (const float*)d_in[8];
    const float* attS  = (const float*)d_in[9];
    const float* attD  = (const float*)d_in[10];
    const float* gatb  = (const float*)d_in[11];
    const float* rW    = (const float*)d_in[12];
    const float* rb    = (const float*)d_in[13];
    float* out = (float*)d_out;

    int N = in_sizes[0];
    int E = in_sizes[1] / 2;
    int nInit = (N + 255) / 256;
    int nA = (N + 63) / 64;
    int nB = (E + 255) / 256;

    k_init<<<nInit + NL + 1, 256>>>(out, out_size, N, nInit, gatW, attS, attD, gatb, rW, rb);
    k_embed_scatter<<<nA + nB, 256>>>(xidx, embed, ei, N, E, nA);

    for (int l = 0; l < NL; l++) {
        int inB = l & 1;
        int outB = inB ^ 1;
        int mode = (l == NL - 1) ? 1 : 0;
        k_node<<<(N + 127) / 128, 256>>>(inB, l, linW, linb, bng, bnb, N);
        k_gather<<<(N + 31) / 32, 256>>>(outB, gatW, gatb, batch, out, l, N, mode);
    }
}